// round 9
// baseline (speedup 1.0000x reference)
#include <cuda_runtime.h>
#include <cuda_bf16.h>
#include <cuda_fp16.h>
#include <cstddef>

#define NMAX   50000
#define EMAX   800000
#define IN_DIM 256
#define HID    128
#define ZDIM   64
#define LN_EPS 1e-5f

// ---------------- device scratch (static, no allocation) ----------------
__device__ __half g_th[(size_t)NMAX * HID];     // GEMM output (X @ W), fp16
__device__ float  g_h [(size_t)NMAX * HID];     // layer output after agg+relu
__device__ float  g_mu[NMAX];
__device__ float  g_rs[NMAX];
__device__ float  g_dinv[NMAX];
__device__ float  g_w  [EMAX];                  // per-edge coef dinv[s]*dinv[d]
__device__ int    g_deg[NMAX];
__device__ int    g_rowptr[NMAX + 1];
__device__ int    g_cursor[NMAX];
__device__ int    g_cidx[EMAX];                 // src indices sorted by dst

__device__ __forceinline__ int clampi(int v, int lo, int hi) {
    return min(max(v, lo), hi);
}

__device__ __forceinline__ float to_tf32(float x) {
    unsigned u;
    asm("cvt.rna.tf32.f32 %0, %1;" : "=r"(u) : "f"(x));
    return __uint_as_float(u);
}

// ---------------- LayerNorm stats: one warp per 256-wide row ----------------
__global__ void ln_stats_kernel(const float* __restrict__ x, int n) {
    int row  = blockIdx.x * 8 + (threadIdx.x >> 5);
    if (row >= n) return;
    int lane = threadIdx.x & 31;
    const float* xr = x + (size_t)row * IN_DIM;

    float4 v0 = *(const float4*)(xr + lane * 8);
    float4 v1 = *(const float4*)(xr + lane * 8 + 4);

    float s  = v0.x + v0.y + v0.z + v0.w + v1.x + v1.y + v1.z + v1.w;
    float sq = v0.x*v0.x + v0.y*v0.y + v0.z*v0.z + v0.w*v0.w
             + v1.x*v1.x + v1.y*v1.y + v1.z*v1.z + v1.w*v1.w;
    #pragma unroll
    for (int off = 16; off > 0; off >>= 1) {
        s  += __shfl_xor_sync(0xffffffffu, s,  off);
        sq += __shfl_xor_sync(0xffffffffu, sq, off);
    }
    if (lane == 0) {
        float mu  = s * (1.0f / IN_DIM);
        float var = sq * (1.0f / IN_DIM) - mu * mu;
        g_mu[row] = mu;
        g_rs[row] = rsqrtf(var + LN_EPS);
    }
}

// ---------------- degree / CSR build ----------------
__global__ void zero_deg_kernel(int n) {
    int i = blockIdx.x * blockDim.x + threadIdx.x;
    if (i < n) g_deg[i] = 0;
}

__global__ void count_kernel(const int* __restrict__ ei, int e, int n) {
    int i = blockIdx.x * blockDim.x + threadIdx.x;
    if (i >= e) return;
    int d = clampi(ei[e + i], 0, n - 1);
    atomicAdd(&g_deg[d], 1);
}

__global__ void dinv_kernel(int n) {
    int i = blockIdx.x * blockDim.x + threadIdx.x;
    if (i < n) g_dinv[i] = rsqrtf(1.0f + (float)g_deg[i]);
}

// single-block exclusive scan of g_deg -> g_rowptr (and g_cursor)
__global__ void scan_kernel(int n) {
    __shared__ int warp_sums[32];
    __shared__ int s_carry;
    int t = threadIdx.x, lane = t & 31, wid = t >> 5;
    if (t == 0) s_carry = 0;
    __syncthreads();
    for (int base = 0; base < n; base += 1024) {
        int i = base + t;
        int v = (i < n) ? g_deg[i] : 0;
        int x = v;
        #pragma unroll
        for (int off = 1; off < 32; off <<= 1) {
            int y = __shfl_up_sync(0xffffffffu, x, off);
            if (lane >= off) x += y;
        }
        if (lane == 31) warp_sums[wid] = x;
        __syncthreads();
        if (wid == 0) {
            int ws = warp_sums[lane];
            #pragma unroll
            for (int off = 1; off < 32; off <<= 1) {
                int y = __shfl_up_sync(0xffffffffu, ws, off);
                if (lane >= off) ws += y;
            }
            warp_sums[lane] = ws;
        }
        __syncthreads();
        int warp_off = (wid == 0) ? 0 : warp_sums[wid - 1];
        int excl = s_carry + warp_off + x - v;
        if (i < n) { g_rowptr[i] = excl; g_cursor[i] = excl; }
        int total = warp_sums[31];
        __syncthreads();
        if (t == 0) s_carry += total;
        __syncthreads();
    }
    if (t == 0) g_rowptr[n] = s_carry;
}

__global__ void scatter_kernel(const int* __restrict__ ei, int e, int n) {
    int i = blockIdx.x * blockDim.x + threadIdx.x;
    if (i >= e) return;
    int s = clampi(ei[i],     0, n - 1);
    int d = clampi(ei[e + i], 0, n - 1);
    int pos = atomicAdd(&g_cursor[d], 1);
    g_cidx[pos] = s;
    g_w[pos] = g_dinv[s] * g_dinv[d];
}

// ---------------- tf32 tensor-core GEMM: g_th[M,NOUT] = A[M,K] @ W[K,NOUT] ---
// BM=32, BK=32, 8 warps as 2 m16 strips x 4 col quarters.
// Fragment-layout smem: A = 1 LDS.128 / octet / warp, B = NT LDS.64.
// This tiling minimizes total smem read bytes (B redundancy 2x, not 4x).
// Output stored fp16. LN=true applies layernorm in the A loader.
template <int K, int NOUT, bool LN>
__launch_bounds__(256, 4)
__global__ void gemm_tc_kernel(const float* __restrict__ Ain,
                               const float* __restrict__ W,
                               const float* __restrict__ gamma,
                               const float* __restrict__ beta, int M) {
    const float* __restrict__ A = LN ? Ain : g_h;
    __half* __restrict__ C = g_th;

    constexpr int BM = 32, BK = 32;
    constexpr int G   = 4;              // col groups
    constexpr int NPW = NOUT / G;       // cols per warp (32 or 16)
    constexpr int NT  = NPW / 8;        // n8 tiles per warp (4 or 2)
    constexpr int NTT = NOUT / 8;       // total n8 tiles (16 or 8)
    constexpr int APAD = 132;           // words per [strip][ks] A block
    constexpr int BPAD = 66;            // words per [ks][ni] B block

    __shared__ alignas(16) float Afrag[2 * 4 * APAD];
    __shared__ alignas(16) float Bfrag[4 * NTT * BPAD];

    int tid  = threadIdx.x;
    int wid  = tid >> 5;
    int lane = tid & 31;
    int qr   = lane >> 2;     // 0..7
    int qc   = lane & 3;      // 0..3
    int wr   = wid >> 2;      // 0..1 : m16 strip
    int wc   = wid & 3;       // 0..3 : col quarter
    int m0   = blockIdx.x * BM;

    float c[NT][4];
    #pragma unroll
    for (int ni = 0; ni < NT; ni++)
        #pragma unroll
        for (int j = 0; j < 4; j++) c[ni][j] = 0.0f;

    for (int kt = 0; kt < K; kt += BK) {
        // ---- A tile: 32 rows x 32 k -> fragment layout, tf32-rounded ----
        int kc = (tid & 7) * 4;           // 0,4,...,28
        {
            int r  = tid >> 3;            // 0..31
            int gr = m0 + r;
            float4 a = make_float4(0.f, 0.f, 0.f, 0.f);
            if (gr < M) {
                a = *(const float4*)(A + (size_t)gr * K + kt + kc);
                if (LN) {
                    float4 gm = *(const float4*)(gamma + kt + kc);
                    float4 bt = *(const float4*)(beta  + kt + kc);
                    float mu = g_mu[gr], rs = g_rs[gr];
                    a.x = (a.x - mu) * rs * gm.x + bt.x;
                    a.y = (a.y - mu) * rs * gm.y + bt.y;
                    a.z = (a.z - mu) * rs * gm.z + bt.z;
                    a.w = (a.w - mu) * rs * gm.w + bt.w;
                }
            }
            int s_   = r >> 4;            // strip 0..1
            int rin  = r & 15;
            int ks   = kc >> 3;
            int aidx = (rin >> 3) + ((kc & 4) ? 2 : 0);
            int base = (s_ * 4 + ks) * APAD + (rin & 7) * 16 + aidx;
            Afrag[base + 0 ] = to_tf32(a.x);
            Afrag[base + 4 ] = to_tf32(a.y);
            Afrag[base + 8 ] = to_tf32(a.z);
            Afrag[base + 12] = to_tf32(a.w);
        }
        // ---- B tile: 32 x NOUT -> fragment layout, tf32-rounded ----
        constexpr int CPR = NOUT / 4;       // float4 loads per row
        constexpr int RPP = 256 / CPR;      // rows per pass
        #pragma unroll
        for (int p = 0; p < BK / RPP; p++) {
            int r  = (tid / CPR) + p * RPP;
            int cc = (tid % CPR) * 4;
            float4 b = *(const float4*)(W + (size_t)(kt + r) * NOUT + cc);
            int ks  = r >> 3;
            int kin = r & 7;
            int jb  = kin >> 2;           // 0 or 1
            int qcb = kin & 3;
            int ni  = cc >> 3;
            int base = (ks * NTT + ni) * BPAD + ((cc & 7) * 4 + qcb) * 2 + jb;
            Bfrag[base + 0 ] = to_tf32(b.x);
            Bfrag[base + 8 ] = to_tf32(b.y);
            Bfrag[base + 16] = to_tf32(b.z);
            Bfrag[base + 24] = to_tf32(b.w);
        }
        __syncthreads();

        #pragma unroll
        for (int ks = 0; ks < BK / 8; ks++) {
            float4 afv = *(const float4*)&Afrag[(wr * 4 + ks) * APAD + lane * 4];
            unsigned a0 = __float_as_uint(afv.x);
            unsigned a1 = __float_as_uint(afv.y);
            unsigned a2 = __float_as_uint(afv.z);
            unsigned a3 = __float_as_uint(afv.w);
            #pragma unroll
            for (int ni = 0; ni < NT; ni++) {
                float2 bv = *(const float2*)
                    &Bfrag[(ks * NTT + wc * NT + ni) * BPAD + lane * 2];
                unsigned b0 = __float_as_uint(bv.x);
                unsigned b1 = __float_as_uint(bv.y);
                asm volatile(
                    "mma.sync.aligned.m16n8k8.row.col.f32.tf32.tf32.f32 "
                    "{%0,%1,%2,%3}, {%4,%5,%6,%7}, {%8,%9}, {%0,%1,%2,%3};"
                    : "+f"(c[ni][0]), "+f"(c[ni][1]),
                      "+f"(c[ni][2]), "+f"(c[ni][3])
                    : "r"(a0), "r"(a1), "r"(a2), "r"(a3),
                      "r"(b0), "r"(b1));
            }
        }
        __syncthreads();
    }

    // epilogue: fp16 output, half2 per (row, 2 cols)
    int row = m0 + wr * 16 + qr;
    #pragma unroll
    for (int ni = 0; ni < NT; ni++) {
        int col = wc * NPW + ni * 8 + 2 * qc;
        if (row < M) {
            *(__half2*)(C + (size_t)row * NOUT + col) =
                __floats2half2_rn(c[ni][0], c[ni][1]);
        }
        if (row + 8 < M) {
            *(__half2*)(C + (size_t)(row + 8) * NOUT + col) =
                __floats2half2_rn(c[ni][2], c[ni][3]);
        }
    }
}

// ---------------- aggregation: out[v] = sum_{(s->v)} t[s]*w + t[v]*dinv[v]^2 + b
// Reads g_th (fp16), accumulates fp32. TO_TMP: true -> g_h, false -> outp.
template <int D, bool RELU, bool TO_TMP>
__global__ void agg_kernel(const float* __restrict__ bias,
                           float* __restrict__ outp, int n) {
    const __half* __restrict__ t = g_th;
    constexpr int GS  = D / 4;        // lanes per row (32 for D=128, 16 for D=64)
    constexpr int GPB = 128 / GS;
    int g = blockIdx.x * GPB + threadIdx.x / GS;
    if (g >= n) return;
    int lane = threadIdx.x % GS;
    int c = lane * 4;

    float dv = g_dinv[g];
    float sc = dv * dv;
    float4 b4 = *(const float4*)(bias + c);

    __half2 sv0, sv1;
    {
        uint2 raw = *(const uint2*)(t + (size_t)g * D + c);
        sv0 = *reinterpret_cast<__half2*>(&raw.x);
        sv1 = *reinterpret_cast<__half2*>(&raw.y);
    }
    float2 f0 = __half22float2(sv0);
    float2 f1 = __half22float2(sv1);
    float4 acc;
    acc.x = f0.x * sc + b4.x;
    acc.y = f0.y * sc + b4.y;
    acc.z = f1.x * sc + b4.z;
    acc.w = f1.y * sc + b4.w;

    int e0 = g_rowptr[g], e1 = g_rowptr[g + 1];
    for (int e = e0; e < e1; e++) {
        int s   = g_cidx[e];
        float w = g_w[e];
        uint2 raw = *(const uint2*)(t + (size_t)s * D + c);
        float2 h0 = __half22float2(*reinterpret_cast<__half2*>(&raw.x));
        float2 h1 = __half22float2(*reinterpret_cast<__half2*>(&raw.y));
        acc.x += h0.x * w;
        acc.y += h0.y * w;
        acc.z += h1.x * w;
        acc.w += h1.y * w;
    }
    if (RELU) {
        acc.x = fmaxf(acc.x, 0.f);
        acc.y = fmaxf(acc.y, 0.f);
        acc.z = fmaxf(acc.z, 0.f);
        acc.w = fmaxf(acc.w, 0.f);
    }
    float* o = TO_TMP ? (g_h + (size_t)g * D + c) : (outp + (size_t)g * D + c);
    *(float4*)o = acc;
}

// ---------------- launch ----------------
extern "C" void kernel_launch(void* const* d_in, const int* in_sizes, int n_in,
                              void* d_out, int out_size) {
    const float* x     = (const float*)d_in[0];
    const int*   ei    = (const int*)d_in[1];     // int32: JAX x64 disabled
    const float* gamma = (const float*)d_in[2];
    const float* beta  = (const float*)d_in[3];
    const float* W1    = (const float*)d_in[4];
    const float* b1    = (const float*)d_in[5];
    const float* W2    = (const float*)d_in[6];
    const float* b2    = (const float*)d_in[7];
    const float* W3    = (const float*)d_in[8];
    const float* b3    = (const float*)d_in[9];
    float* out = (float*)d_out;

    int n = in_sizes[0] / IN_DIM;   // 50000
    int e = in_sizes[1] / 2;        // 800000

    // LayerNorm row stats (mu, rstd) — LN applied inside GEMM1 loader
    ln_stats_kernel<<<(n + 7) / 8, 256>>>(x, n);

    // CSR build interleaved with GEMM1 so the ncu capture slot (4th launch)
    // lands on the tensor-core GEMM.
    zero_deg_kernel<<<(n + 255) / 256, 256>>>(n);
    count_kernel<<<(e + 255) / 256, 256>>>(ei, e, n);

    // layer 1 GEMM: 256 -> 128 (LN fused into A load)
    gemm_tc_kernel<IN_DIM, HID, true><<<(n + 31) / 32, 256>>>(x, W1, gamma, beta, n);

    dinv_kernel<<<(n + 255) / 256, 256>>>(n);
    scan_kernel<<<1, 1024>>>(n);
    scatter_kernel<<<(e + 255) / 256, 256>>>(ei, e, n);

    agg_kernel<HID, true, true><<<(n + 3) / 4, 128>>>(b1, nullptr, n);

    // layer 2: 128 -> 128, relu
    gemm_tc_kernel<HID, HID, false><<<(n + 31) / 32, 256>>>(nullptr, W2, nullptr, nullptr, n);
    agg_kernel<HID, true, true><<<(n + 3) / 4, 128>>>(b2, nullptr, n);

    // layer 3: 128 -> 64, no relu, writes d_out
    gemm_tc_kernel<HID, ZDIM, false><<<(n + 31) / 32, 256>>>(nullptr, W3, nullptr, nullptr, n);
    agg_kernel<ZDIM, false, false><<<(n + 7) / 8, 128>>>(b3, out, n);
}

// round 11
// speedup vs baseline: 1.1311x; 1.1311x over previous
#include <cuda_runtime.h>
#include <cuda_bf16.h>
#include <cuda_fp16.h>
#include <cstddef>

#define NMAX   50000
#define EMAX   800000
#define IN_DIM 256
#define HID    128
#define ZDIM   64
#define LN_EPS 1e-5f

// ---------------- device scratch (static, no allocation) ----------------
__device__ __half g_th[(size_t)NMAX * HID];     // GEMM output (X @ W), fp16
__device__ float  g_h [(size_t)NMAX * HID];     // layer output after agg+relu
__device__ float  g_mu[NMAX];
__device__ float  g_rs[NMAX];
__device__ float  g_dinv[NMAX];
__device__ float  g_w  [EMAX];                  // per-edge coef dinv[s]*dinv[d]
__device__ int    g_deg[NMAX];
__device__ int    g_rowptr[NMAX + 1];
__device__ int    g_cursor[NMAX];
__device__ int    g_cidx[EMAX];                 // src indices sorted by dst

__device__ __forceinline__ int clampi(int v, int lo, int hi) {
    return min(max(v, lo), hi);
}

// ---------------- LayerNorm stats: one warp per 256-wide row ----------------
__global__ void ln_stats_kernel(const float* __restrict__ x, int n) {
    int row  = blockIdx.x * 8 + (threadIdx.x >> 5);
    if (row >= n) return;
    int lane = threadIdx.x & 31;
    const float* xr = x + (size_t)row * IN_DIM;

    float4 v0 = *(const float4*)(xr + lane * 8);
    float4 v1 = *(const float4*)(xr + lane * 8 + 4);

    float s  = v0.x + v0.y + v0.z + v0.w + v1.x + v1.y + v1.z + v1.w;
    float sq = v0.x*v0.x + v0.y*v0.y + v0.z*v0.z + v0.w*v0.w
             + v1.x*v1.x + v1.y*v1.y + v1.z*v1.z + v1.w*v1.w;
    #pragma unroll
    for (int off = 16; off > 0; off >>= 1) {
        s  += __shfl_xor_sync(0xffffffffu, s,  off);
        sq += __shfl_xor_sync(0xffffffffu, sq, off);
    }
    if (lane == 0) {
        float mu  = s * (1.0f / IN_DIM);
        float var = sq * (1.0f / IN_DIM) - mu * mu;
        g_mu[row] = mu;
        g_rs[row] = rsqrtf(var + LN_EPS);
    }
}

// ---------------- degree / CSR build ----------------
__global__ void zero_deg_kernel(int n) {
    int i = blockIdx.x * blockDim.x + threadIdx.x;
    if (i < n) g_deg[i] = 0;
}

__global__ void count_kernel(const int* __restrict__ ei, int e, int n) {
    int i = blockIdx.x * blockDim.x + threadIdx.x;
    if (i >= e) return;
    int d = clampi(ei[e + i], 0, n - 1);
    atomicAdd(&g_deg[d], 1);
}

__global__ void dinv_kernel(int n) {
    int i = blockIdx.x * blockDim.x + threadIdx.x;
    if (i < n) g_dinv[i] = rsqrtf(1.0f + (float)g_deg[i]);
}

// single-block exclusive scan of g_deg -> g_rowptr (and g_cursor)
__global__ void scan_kernel(int n) {
    __shared__ int warp_sums[32];
    __shared__ int s_carry;
    int t = threadIdx.x, lane = t & 31, wid = t >> 5;
    if (t == 0) s_carry = 0;
    __syncthreads();
    for (int base = 0; base < n; base += 1024) {
        int i = base + t;
        int v = (i < n) ? g_deg[i] : 0;
        int x = v;
        #pragma unroll
        for (int off = 1; off < 32; off <<= 1) {
            int y = __shfl_up_sync(0xffffffffu, x, off);
            if (lane >= off) x += y;
        }
        if (lane == 31) warp_sums[wid] = x;
        __syncthreads();
        if (wid == 0) {
            int ws = warp_sums[lane];
            #pragma unroll
            for (int off = 1; off < 32; off <<= 1) {
                int y = __shfl_up_sync(0xffffffffu, ws, off);
                if (lane >= off) ws += y;
            }
            warp_sums[lane] = ws;
        }
        __syncthreads();
        int warp_off = (wid == 0) ? 0 : warp_sums[wid - 1];
        int excl = s_carry + warp_off + x - v;
        if (i < n) { g_rowptr[i] = excl; g_cursor[i] = excl; }
        int total = warp_sums[31];
        __syncthreads();
        if (t == 0) s_carry += total;
        __syncthreads();
    }
    if (t == 0) g_rowptr[n] = s_carry;
}

__global__ void scatter_kernel(const int* __restrict__ ei, int e, int n) {
    int i = blockIdx.x * blockDim.x + threadIdx.x;
    if (i >= e) return;
    int s = clampi(ei[i],     0, n - 1);
    int d = clampi(ei[e + i], 0, n - 1);
    int pos = atomicAdd(&g_cursor[d], 1);
    g_cidx[pos] = s;
    g_w[pos] = g_dinv[s] * g_dinv[d];
}

// ---------------- fp16 tensor-core GEMM: g_th[M,NOUT] = A[M,K] @ W[K,NOUT] ---
// mma.sync.m16n8k16.f32.f16.f16.f32. BM=64, BK=32 (2 k16 steps per tile).
// 8 warps as 4 m16 strips x 2 col halves. Fragment-layout fp16 smem:
//   A: 1 LDS.128 per k16 per warp.  B: 1 LDS.64 per (k16, n8-tile).
// Accumulate fp32, store fp16. LN=true applies layernorm in the A loader.
template <int K, int NOUT, bool LN>
__launch_bounds__(256, 3)
__global__ void gemm_tc_kernel(const float* __restrict__ Ain,
                               const float* __restrict__ W,
                               const float* __restrict__ gamma,
                               const float* __restrict__ beta, int M) {
    const float* __restrict__ A = LN ? Ain : g_h;
    __half* __restrict__ C = g_th;

    constexpr int BM = 64, BK = 32;
    constexpr int NPW = NOUT / 2;       // cols per warp (64 or 32)
    constexpr int NT  = NPW / 8;        // n8 tiles per warp (8 or 4)
    constexpr int NTT = NOUT / 8;       // total n8 tiles (16 or 8)
    constexpr int ABLK = 132;           // uints per [strip][kstep] A block
    constexpr int BBLK = 136;           // halves per [kstep][ni] B block

    __shared__ alignas(16) unsigned Ah[4 * 2 * ABLK];
    __shared__ alignas(16) __half  Bh[2 * NTT * BBLK];

    int tid  = threadIdx.x;
    int wid  = tid >> 5;
    int lane = tid & 31;
    int qr   = lane >> 2;     // 0..7
    int qc   = lane & 3;      // 0..3
    int wr   = wid >> 1;      // 0..3 : m16 strip
    int wc   = wid & 1;       // 0..1 : col half
    int m0   = blockIdx.x * BM;

    float c[NT][4];
    #pragma unroll
    for (int ni = 0; ni < NT; ni++)
        #pragma unroll
        for (int j = 0; j < 4; j++) c[ni][j] = 0.0f;

    for (int kt = 0; kt < K; kt += BK) {
        // ---- A tile: 64 rows x 32 k -> fp16 fragment layout ----
        int kc = (tid & 7) * 4;           // 0,4,...,28
        float4 gm, bt;
        if (LN) {
            gm = *(const float4*)(gamma + kt + kc);
            bt = *(const float4*)(beta  + kt + kc);
        }
        #pragma unroll
        for (int p = 0; p < 2; p++) {
            int r  = (tid >> 3) + p * 32;
            int gr = m0 + r;
            float4 a = make_float4(0.f, 0.f, 0.f, 0.f);
            if (gr < M) {
                a = *(const float4*)(A + (size_t)gr * K + kt + kc);
                if (LN) {
                    float mu = g_mu[gr], rs = g_rs[gr];
                    a.x = (a.x - mu) * rs * gm.x + bt.x;
                    a.y = (a.y - mu) * rs * gm.y + bt.y;
                    a.z = (a.z - mu) * rs * gm.z + bt.z;
                    a.w = (a.w - mu) * rs * gm.w + bt.w;
                }
            }
            int s_    = r >> 4;
            int rin   = r & 15;
            int kstep = kc >> 4;
            int kk    = kc & 15;
            int lzero = (rin & 7) * 4 + ((kk & 7) >> 1);
            int reg   = ((rin >> 3) & 1) + ((kk & 8) ? 2 : 0);
            int base  = (s_ * 2 + kstep) * ABLK;
            __half2 h01 = __floats2half2_rn(a.x, a.y);
            __half2 h23 = __floats2half2_rn(a.z, a.w);
            Ah[base + lzero * 4 + reg]       = *reinterpret_cast<unsigned*>(&h01);
            Ah[base + (lzero + 1) * 4 + reg] = *reinterpret_cast<unsigned*>(&h23);
        }
        // ---- B tile: 32 k x NOUT -> fp16 fragment layout ----
        // each lane owns 4 halves per (kstep, ni) block: lane*4 + reg*2 + h
        constexpr int CPR = NOUT / 4;
        constexpr int RPP = 256 / CPR;
        #pragma unroll
        for (int p = 0; p < BK / RPP; p++) {
            int r  = (tid / CPR) + p * RPP;
            int cc = (tid % CPR) * 4;
            float4 b = *(const float4*)(W + (size_t)(kt + r) * NOUT + cc);
            int kstep = r >> 4;
            int kk    = r & 15;
            int reg   = (kk & 8) ? 1 : 0;
            int h     = kk & 1;
            int ni    = cc >> 3;
            int base  = (kstep * NTT + ni) * BBLK + reg * 2 + h;
            int lsub  = (kk & 7) >> 1;
            float bv[4] = {b.x, b.y, b.z, b.w};
            #pragma unroll
            for (int j = 0; j < 4; j++) {
                int col = cc + j;
                int lnB = (col & 7) * 4 + lsub;
                Bh[base + lnB * 4] = __float2half_rn(bv[j]);
            }
        }
        __syncthreads();

        #pragma unroll
        for (int kstep = 0; kstep < 2; kstep++) {
            uint4 af = *(const uint4*)&Ah[(wr * 2 + kstep) * ABLK + lane * 4];
            #pragma unroll
            for (int ni = 0; ni < NT; ni++) {
                uint2 bf = *(const uint2*)
                    &Bh[(kstep * NTT + wc * NT + ni) * BBLK + lane * 4];
                asm volatile(
                    "mma.sync.aligned.m16n8k16.row.col.f32.f16.f16.f32 "
                    "{%0,%1,%2,%3}, {%4,%5,%6,%7}, {%8,%9}, {%0,%1,%2,%3};"
                    : "+f"(c[ni][0]), "+f"(c[ni][1]),
                      "+f"(c[ni][2]), "+f"(c[ni][3])
                    : "r"(af.x), "r"(af.y), "r"(af.z), "r"(af.w),
                      "r"(bf.x), "r"(bf.y));
            }
        }
        __syncthreads();
    }

    int row = m0 + wr * 16 + qr;
    #pragma unroll
    for (int ni = 0; ni < NT; ni++) {
        int col = wc * NPW + ni * 8 + 2 * qc;
        if (row < M) {
            *(__half2*)(C + (size_t)row * NOUT + col) =
                __floats2half2_rn(c[ni][0], c[ni][1]);
        }
        if (row + 8 < M) {
            *(__half2*)(C + (size_t)(row + 8) * NOUT + col) =
                __floats2half2_rn(c[ni][2], c[ni][3]);
        }
    }
}

// ---------------- aggregation: out[v] = sum_{(s->v)} t[s]*w + t[v]*dinv[v]^2 + b
template <int D, bool RELU, bool TO_TMP>
__global__ void agg_kernel(const float* __restrict__ bias,
                           float* __restrict__ outp, int n) {
    const __half* __restrict__ t = g_th;
    constexpr int GS  = D / 4;
    constexpr int GPB = 128 / GS;
    int g = blockIdx.x * GPB + threadIdx.x / GS;
    if (g >= n) return;
    int lane = threadIdx.x % GS;
    int c = lane * 4;

    float dv = g_dinv[g];
    float sc = dv * dv;
    float4 b4 = *(const float4*)(bias + c);

    __half2 sv0, sv1;
    {
        uint2 raw = *(const uint2*)(t + (size_t)g * D + c);
        sv0 = *reinterpret_cast<__half2*>(&raw.x);
        sv1 = *reinterpret_cast<__half2*>(&raw.y);
    }
    float2 f0 = __half22float2(sv0);
    float2 f1 = __half22float2(sv1);
    float4 acc;
    acc.x = f0.x * sc + b4.x;
    acc.y = f0.y * sc + b4.y;
    acc.z = f1.x * sc + b4.z;
    acc.w = f1.y * sc + b4.w;

    int e0 = g_rowptr[g], e1 = g_rowptr[g + 1];
    for (int e = e0; e < e1; e++) {
        int s   = g_cidx[e];
        float w = g_w[e];
        uint2 raw = *(const uint2*)(t + (size_t)s * D + c);
        float2 h0 = __half22float2(*reinterpret_cast<__half2*>(&raw.x));
        float2 h1 = __half22float2(*reinterpret_cast<__half2*>(&raw.y));
        acc.x += h0.x * w;
        acc.y += h0.y * w;
        acc.z += h1.x * w;
        acc.w += h1.y * w;
    }
    if (RELU) {
        acc.x = fmaxf(acc.x, 0.f);
        acc.y = fmaxf(acc.y, 0.f);
        acc.z = fmaxf(acc.z, 0.f);
        acc.w = fmaxf(acc.w, 0.f);
    }
    float* o = TO_TMP ? (g_h + (size_t)g * D + c) : (outp + (size_t)g * D + c);
    *(float4*)o = acc;
}

// ---------------- launch ----------------
extern "C" void kernel_launch(void* const* d_in, const int* in_sizes, int n_in,
                              void* d_out, int out_size) {
    const float* x     = (const float*)d_in[0];
    const int*   ei    = (const int*)d_in[1];
    const float* gamma = (const float*)d_in[2];
    const float* beta  = (const float*)d_in[3];
    const float* W1    = (const float*)d_in[4];
    const float* b1    = (const float*)d_in[5];
    const float* W2    = (const float*)d_in[6];
    const float* b2    = (const float*)d_in[7];
    const float* W3    = (const float*)d_in[8];
    const float* b3    = (const float*)d_in[9];
    float* out = (float*)d_out;

    int n = in_sizes[0] / IN_DIM;
    int e = in_sizes[1] / 2;

    ln_stats_kernel<<<(n + 7) / 8, 256>>>(x, n);

    zero_deg_kernel<<<(n + 255) / 256, 256>>>(n);
    count_kernel<<<(e + 255) / 256, 256>>>(ei, e, n);

    gemm_tc_kernel<IN_DIM, HID, true><<<(n + 63) / 64, 256>>>(x, W1, gamma, beta, n);

    dinv_kernel<<<(n + 255) / 256, 256>>>(n);
    scan_kernel<<<1, 1024>>>(n);
    scatter_kernel<<<(e + 255) / 256, 256>>>(ei, e, n);

    agg_kernel<HID, true, true><<<(n + 3) / 4, 128>>>(b1, nullptr, n);

    gemm_tc_kernel<HID, HID, false><<<(n + 63) / 64, 256>>>(nullptr, W2, nullptr, nullptr, n);
    agg_kernel<HID, true, true><<<(n + 3) / 4, 128>>>(b2, nullptr, n);

    gemm_tc_kernel<HID, ZDIM, false><<<(n + 63) / 64, 256>>>(nullptr, W3, nullptr, nullptr, n);
    agg_kernel<ZDIM, false, false><<<(n + 7) / 8, 128>>>(b3, out, n);
}

// round 12
// speedup vs baseline: 1.1434x; 1.0108x over previous
#include <cuda_runtime.h>
#include <cuda_bf16.h>
#include <cuda_fp16.h>
#include <cstddef>

#define NMAX   50000
#define EMAX   800000
#define IN_DIM 256
#define HID    128
#define ZDIM   64
#define LN_EPS 1e-5f

// ---------------- device scratch (static, no allocation) ----------------
__device__ __half   g_th[(size_t)NMAX * HID];   // GEMM output (X @ W), fp16
__device__ float    g_h [(size_t)NMAX * HID];   // layer output after agg+relu
__device__ float    g_mu[NMAX];
__device__ float    g_rs[NMAX];
__device__ float    g_dinv[NMAX];
__device__ float    g_w  [EMAX];                // per-edge coef dinv[s]*dinv[d]
__device__ int      g_deg[NMAX];
__device__ int      g_rowptr[NMAX + 1];
__device__ int      g_cursor[NMAX];
__device__ int      g_cidx[EMAX];               // src indices sorted by dst
// pre-packed W in mma B-fragment order (uint = half2)
__device__ unsigned g_w1p[(IN_DIM/16) * (HID/8)  * 64];  // 16384
__device__ unsigned g_w2p[(HID/16)    * (HID/8)  * 64];  // 8192
__device__ unsigned g_w3p[(HID/16)    * (ZDIM/8) * 64];  // 4096

__device__ __forceinline__ int clampi(int v, int lo, int hi) {
    return min(max(v, lo), hi);
}

// ---------------- W pre-pack: fragment order for m16n8k16 B operand --------
// uint index u = ((ksg*NTT + ni)*32 + lane)*2 + reg
//   col = ni*8 + (lane>>2);  k = ksg*16 + (lane&3)*2 + reg*8
//   value = half2( W[k][col], W[k+1][col] )
template <int K, int NOUT, int SEL>
__global__ void wpack_kernel(const float* __restrict__ W) {
    unsigned* dst = (SEL == 1) ? g_w1p : (SEL == 2) ? g_w2p : g_w3p;
    constexpr int NTT = NOUT / 8;
    constexpr int TOT = (K / 16) * NTT * 64;
    int u = blockIdx.x * blockDim.x + threadIdx.x;
    if (u >= TOT) return;
    int reg  = u & 1;
    int lane = (u >> 1) & 31;
    int rest = u >> 6;
    int ni   = rest % NTT;
    int ksg  = rest / NTT;
    int col  = ni * 8 + (lane >> 2);
    int k    = ksg * 16 + (lane & 3) * 2 + reg * 8;
    __half2 h = __floats2half2_rn(W[(size_t)k * NOUT + col],
                                  W[(size_t)(k + 1) * NOUT + col]);
    dst[u] = *reinterpret_cast<unsigned*>(&h);
}

// ---------------- LayerNorm stats: one warp per 256-wide row ----------------
__global__ void ln_stats_kernel(const float* __restrict__ x, int n) {
    int row  = blockIdx.x * 8 + (threadIdx.x >> 5);
    if (row >= n) return;
    int lane = threadIdx.x & 31;
    const float* xr = x + (size_t)row * IN_DIM;

    float4 v0 = *(const float4*)(xr + lane * 8);
    float4 v1 = *(const float4*)(xr + lane * 8 + 4);

    float s  = v0.x + v0.y + v0.z + v0.w + v1.x + v1.y + v1.z + v1.w;
    float sq = v0.x*v0.x + v0.y*v0.y + v0.z*v0.z + v0.w*v0.w
             + v1.x*v1.x + v1.y*v1.y + v1.z*v1.z + v1.w*v1.w;
    #pragma unroll
    for (int off = 16; off > 0; off >>= 1) {
        s  += __shfl_xor_sync(0xffffffffu, s,  off);
        sq += __shfl_xor_sync(0xffffffffu, sq, off);
    }
    if (lane == 0) {
        float mu  = s * (1.0f / IN_DIM);
        float var = sq * (1.0f / IN_DIM) - mu * mu;
        g_mu[row] = mu;
        g_rs[row] = rsqrtf(var + LN_EPS);
    }
}

// ---------------- degree / CSR build ----------------
__global__ void zero_deg_kernel(int n) {
    int i = blockIdx.x * blockDim.x + threadIdx.x;
    if (i < n) g_deg[i] = 0;
}

__global__ void count_kernel(const int* __restrict__ ei, int e, int n) {
    int i = blockIdx.x * blockDim.x + threadIdx.x;
    if (i >= e) return;
    int d = clampi(ei[e + i], 0, n - 1);
    atomicAdd(&g_deg[d], 1);
}

__global__ void dinv_kernel(int n) {
    int i = blockIdx.x * blockDim.x + threadIdx.x;
    if (i < n) g_dinv[i] = rsqrtf(1.0f + (float)g_deg[i]);
}

// single-block exclusive scan of g_deg -> g_rowptr (and g_cursor)
__global__ void scan_kernel(int n) {
    __shared__ int warp_sums[32];
    __shared__ int s_carry;
    int t = threadIdx.x, lane = t & 31, wid = t >> 5;
    if (t == 0) s_carry = 0;
    __syncthreads();
    for (int base = 0; base < n; base += 1024) {
        int i = base + t;
        int v = (i < n) ? g_deg[i] : 0;
        int x = v;
        #pragma unroll
        for (int off = 1; off < 32; off <<= 1) {
            int y = __shfl_up_sync(0xffffffffu, x, off);
            if (lane >= off) x += y;
        }
        if (lane == 31) warp_sums[wid] = x;
        __syncthreads();
        if (wid == 0) {
            int ws = warp_sums[lane];
            #pragma unroll
            for (int off = 1; off < 32; off <<= 1) {
                int y = __shfl_up_sync(0xffffffffu, ws, off);
                if (lane >= off) ws += y;
            }
            warp_sums[lane] = ws;
        }
        __syncthreads();
        int warp_off = (wid == 0) ? 0 : warp_sums[wid - 1];
        int excl = s_carry + warp_off + x - v;
        if (i < n) { g_rowptr[i] = excl; g_cursor[i] = excl; }
        int total = warp_sums[31];
        __syncthreads();
        if (t == 0) s_carry += total;
        __syncthreads();
    }
    if (t == 0) g_rowptr[n] = s_carry;
}

__global__ void scatter_kernel(const int* __restrict__ ei, int e, int n) {
    int i = blockIdx.x * blockDim.x + threadIdx.x;
    if (i >= e) return;
    int s = clampi(ei[i],     0, n - 1);
    int d = clampi(ei[e + i], 0, n - 1);
    int pos = atomicAdd(&g_cursor[d], 1);
    g_cidx[pos] = s;
    g_w[pos] = g_dinv[s] * g_dinv[d];
}

// ---------------- fp16 tensor-core GEMM: g_th[M,NOUT] = A[M,K] @ W[K,NOUT] ---
// m16n8k16 fp16 MMA, fp32 accumulate. BM=64, BK=32.
// A: double-buffered smem in fragment layout (1 LDS.128 / k16 / warp),
//    next tile prefetched into registers during MMA phase.
// B: direct LDG.64 from pre-packed fragment-order W (L2-resident), no smem.
// One __syncthreads per tile.
template <int K, int NOUT, bool LN, int WSEL>
__launch_bounds__(256, 3)
__global__ void gemm_tc_kernel(const float* __restrict__ Ain,
                               const float* __restrict__ gamma,
                               const float* __restrict__ beta, int M) {
    const float* __restrict__ A = LN ? Ain : g_h;
    const unsigned* __restrict__ Wp =
        (WSEL == 1) ? g_w1p : (WSEL == 2) ? g_w2p : g_w3p;
    __half* __restrict__ C = g_th;

    constexpr int BM  = 64;
    constexpr int NPW = NOUT / 2;
    constexpr int NT  = NPW / 8;
    constexpr int NTT = NOUT / 8;
    constexpr int ABLK  = 132;          // uints per [strip][kstep] block
    constexpr int TILES = K / 32;

    __shared__ alignas(16) unsigned Ah[2][8 * ABLK];

    int tid  = threadIdx.x;
    int wid  = tid >> 5;
    int lane = tid & 31;
    int qr   = lane >> 2;
    int qc   = lane & 3;
    int wr   = wid >> 1;      // m16 strip
    int wc   = wid & 1;       // col half
    int m0   = blockIdx.x * BM;

    // A loader / store indices (fixed per thread)
    int kc     = (tid & 7) * 4;          // k offset within 32-tile
    int kstepL = kc >> 4;
    int lsubA  = ((kc & 15) & 7) >> 1;
    int khalf  = ((kc & 15) & 8) ? 2 : 0;

    float4 apref[2];
    float4 gm, bt;

    auto loadA = [&](int t) {
        int kt = t * 32;
        if (LN) {
            gm = *(const float4*)(gamma + kt + kc);
            bt = *(const float4*)(beta  + kt + kc);
        }
        #pragma unroll
        for (int p = 0; p < 2; p++) {
            int r  = (tid >> 3) + p * 32;
            int gr = m0 + r;
            float4 a = make_float4(0.f, 0.f, 0.f, 0.f);
            if (gr < M) {
                a = *(const float4*)(A + (size_t)gr * K + kt + kc);
                if (LN) {
                    float mu = g_mu[gr], rs = g_rs[gr];
                    a.x = (a.x - mu) * rs * gm.x + bt.x;
                    a.y = (a.y - mu) * rs * gm.y + bt.y;
                    a.z = (a.z - mu) * rs * gm.z + bt.z;
                    a.w = (a.w - mu) * rs * gm.w + bt.w;
                }
            }
            apref[p] = a;
        }
    };
    auto storeA = [&](int buf) {
        #pragma unroll
        for (int p = 0; p < 2; p++) {
            int r   = (tid >> 3) + p * 32;
            int s_  = r >> 4;
            int rin = r & 15;
            int lzero = (rin & 7) * 4 + lsubA;
            int reg   = ((rin >> 3) & 1) + khalf;
            unsigned* base = &Ah[buf][(s_ * 2 + kstepL) * ABLK];
            __half2 h01 = __floats2half2_rn(apref[p].x, apref[p].y);
            __half2 h23 = __floats2half2_rn(apref[p].z, apref[p].w);
            base[lzero * 4 + reg]       = *reinterpret_cast<unsigned*>(&h01);
            base[(lzero + 1) * 4 + reg] = *reinterpret_cast<unsigned*>(&h23);
        }
    };

    float c[NT][4];
    #pragma unroll
    for (int ni = 0; ni < NT; ni++)
        #pragma unroll
        for (int j = 0; j < 4; j++) c[ni][j] = 0.0f;

    loadA(0);
    storeA(0);
    __syncthreads();

    for (int t = 0; t < TILES; t++) {
        // B fragments for this tile: direct coalesced LDG from packed W
        uint2 bf[2][NT];
        #pragma unroll
        for (int ks = 0; ks < 2; ks++)
            #pragma unroll
            for (int ni = 0; ni < NT; ni++)
                bf[ks][ni] = __ldg((const uint2*)(Wp +
                    (((t * 2 + ks) * NTT + wc * NT + ni) * 64 + lane * 2)));

        if (t + 1 < TILES) loadA(t + 1);

        #pragma unroll
        for (int ks = 0; ks < 2; ks++) {
            uint4 af = *(const uint4*)&Ah[t & 1][(wr * 2 + ks) * ABLK + lane * 4];
            #pragma unroll
            for (int ni = 0; ni < NT; ni++) {
                asm volatile(
                    "mma.sync.aligned.m16n8k16.row.col.f32.f16.f16.f32 "
                    "{%0,%1,%2,%3}, {%4,%5,%6,%7}, {%8,%9}, {%0,%1,%2,%3};"
                    : "+f"(c[ni][0]), "+f"(c[ni][1]),
                      "+f"(c[ni][2]), "+f"(c[ni][3])
                    : "r"(af.x), "r"(af.y), "r"(af.z), "r"(af.w),
                      "r"(bf[ks][ni].x), "r"(bf[ks][ni].y));
            }
        }

        if (t + 1 < TILES) storeA((t + 1) & 1);
        __syncthreads();
    }

    int row = m0 + wr * 16 + qr;
    #pragma unroll
    for (int ni = 0; ni < NT; ni++) {
        int col = wc * NPW + ni * 8 + 2 * qc;
        if (row < M) {
            *(__half2*)(C + (size_t)row * NOUT + col) =
                __floats2half2_rn(c[ni][0], c[ni][1]);
        }
        if (row + 8 < M) {
            *(__half2*)(C + (size_t)(row + 8) * NOUT + col) =
                __floats2half2_rn(c[ni][2], c[ni][3]);
        }
    }
}

// ---------------- aggregation: out[v] = sum_{(s->v)} t[s]*w + t[v]*dinv[v]^2 + b
template <int D, bool RELU, bool TO_TMP>
__global__ void agg_kernel(const float* __restrict__ bias,
                           float* __restrict__ outp, int n) {
    const __half* __restrict__ t = g_th;
    constexpr int GS  = D / 4;
    constexpr int GPB = 128 / GS;
    int g = blockIdx.x * GPB + threadIdx.x / GS;
    if (g >= n) return;
    int lane = threadIdx.x % GS;
    int c = lane * 4;

    float dv = g_dinv[g];
    float sc = dv * dv;
    float4 b4 = *(const float4*)(bias + c);

    __half2 sv0, sv1;
    {
        uint2 raw = *(const uint2*)(t + (size_t)g * D + c);
        sv0 = *reinterpret_cast<__half2*>(&raw.x);
        sv1 = *reinterpret_cast<__half2*>(&raw.y);
    }
    float2 f0 = __half22float2(sv0);
    float2 f1 = __half22float2(sv1);
    float4 acc;
    acc.x = f0.x * sc + b4.x;
    acc.y = f0.y * sc + b4.y;
    acc.z = f1.x * sc + b4.z;
    acc.w = f1.y * sc + b4.w;

    int e0 = g_rowptr[g], e1 = g_rowptr[g + 1];
    for (int e = e0; e < e1; e++) {
        int s   = g_cidx[e];
        float w = g_w[e];
        uint2 raw = *(const uint2*)(t + (size_t)s * D + c);
        float2 h0 = __half22float2(*reinterpret_cast<__half2*>(&raw.x));
        float2 h1 = __half22float2(*reinterpret_cast<__half2*>(&raw.y));
        acc.x += h0.x * w;
        acc.y += h0.y * w;
        acc.z += h1.x * w;
        acc.w += h1.y * w;
    }
    if (RELU) {
        acc.x = fmaxf(acc.x, 0.f);
        acc.y = fmaxf(acc.y, 0.f);
        acc.z = fmaxf(acc.z, 0.f);
        acc.w = fmaxf(acc.w, 0.f);
    }
    float* o = TO_TMP ? (g_h + (size_t)g * D + c) : (outp + (size_t)g * D + c);
    *(float4*)o = acc;
}

// ---------------- launch ----------------
extern "C" void kernel_launch(void* const* d_in, const int* in_sizes, int n_in,
                              void* d_out, int out_size) {
    const float* x     = (const float*)d_in[0];
    const int*   ei    = (const int*)d_in[1];
    const float* gamma = (const float*)d_in[2];
    const float* beta  = (const float*)d_in[3];
    const float* W1    = (const float*)d_in[4];
    const float* b1    = (const float*)d_in[5];
    const float* W2    = (const float*)d_in[6];
    const float* b2    = (const float*)d_in[7];
    const float* W3    = (const float*)d_in[8];
    const float* b3    = (const float*)d_in[9];
    float* out = (float*)d_out;

    int n = in_sizes[0] / IN_DIM;
    int e = in_sizes[1] / 2;

    // pack W1, LN stats, zero -> gemm1 at launch slot 4 (ncu capture lands there)
    wpack_kernel<IN_DIM, HID, 1><<<(16384 + 255) / 256, 256>>>(W1);
    ln_stats_kernel<<<(n + 7) / 8, 256>>>(x, n);
    zero_deg_kernel<<<(n + 255) / 256, 256>>>(n);

    gemm_tc_kernel<IN_DIM, HID, true, 1><<<(n + 63) / 64, 256>>>(x, gamma, beta, n);

    count_kernel<<<(e + 255) / 256, 256>>>(ei, e, n);
    wpack_kernel<HID, HID, 2><<<(8192 + 255) / 256, 256>>>(W2);
    wpack_kernel<HID, ZDIM, 3><<<(4096 + 255) / 256, 256>>>(W3);
    dinv_kernel<<<(n + 255) / 256, 256>>>(n);
    scan_kernel<<<1, 1024>>>(n);
    scatter_kernel<<<(e + 255) / 256, 256>>>(ei, e, n);

    agg_kernel<HID, true, true><<<(n + 3) / 4, 128>>>(b1, nullptr, n);

    gemm_tc_kernel<HID, HID, false, 2><<<(n + 63) / 64, 256>>>(nullptr, nullptr, nullptr, n);
    agg_kernel<HID, true, true><<<(n + 3) / 4, 128>>>(b2, nullptr, n);

    gemm_tc_kernel<HID, ZDIM, false, 3><<<(n + 63) / 64, 256>>>(nullptr, nullptr, nullptr, n);
    agg_kernel<ZDIM, false, false><<<(n + 7) / 8, 128>>>(b3, out, n);
}

// round 13
// speedup vs baseline: 1.3519x; 1.1823x over previous
#include <cuda_runtime.h>
#include <cuda_bf16.h>
#include <cuda_fp16.h>
#include <cstddef>

#define NMAX   50000
#define EMAX   800000
#define IN_DIM 256
#define HID    128
#define ZDIM   64
#define LN_EPS 1e-5f

// ---------------- device scratch (static, no allocation) ----------------
__device__ __half   g_th[(size_t)NMAX * HID];   // GEMM output (X @ W), fp16
__device__ __half   g_hh[(size_t)NMAX * HID];   // layer output after agg+relu, fp16
__device__ float    g_mu[NMAX];
__device__ float    g_rs[NMAX];
__device__ float    g_dinv[NMAX];
__device__ float    g_w  [EMAX];                // per-edge coef dinv[s]*dinv[d]
__device__ int      g_deg[NMAX];
__device__ int      g_rowptr[NMAX + 1];
__device__ int      g_cursor[NMAX];
__device__ int      g_cidx[EMAX];               // src indices sorted by dst
__device__ int      g_bsum[256];
__device__ int      g_boff[256];
// pre-packed W in mma B-fragment order (uint = half2)
__device__ unsigned g_w1p[(IN_DIM/16) * (HID/8)  * 64];  // 16384
__device__ unsigned g_w2p[(HID/16)    * (HID/8)  * 64];  // 8192
__device__ unsigned g_w3p[(HID/16)    * (ZDIM/8) * 64];  // 4096

__device__ __forceinline__ int clampi(int v, int lo, int hi) {
    return min(max(v, lo), hi);
}

// ---------------- W pre-pack: fragment order for m16n8k16 B operand --------
template <int K, int NOUT, int SEL>
__global__ void wpack_kernel(const float* __restrict__ W) {
    unsigned* dst = (SEL == 1) ? g_w1p : (SEL == 2) ? g_w2p : g_w3p;
    constexpr int NTT = NOUT / 8;
    constexpr int TOT = (K / 16) * NTT * 64;
    int u = blockIdx.x * blockDim.x + threadIdx.x;
    if (u >= TOT) return;
    int reg  = u & 1;
    int lane = (u >> 1) & 31;
    int rest = u >> 6;
    int ni   = rest % NTT;
    int ksg  = rest / NTT;
    int col  = ni * 8 + (lane >> 2);
    int k    = ksg * 16 + (lane & 3) * 2 + reg * 8;
    __half2 h = __floats2half2_rn(W[(size_t)k * NOUT + col],
                                  W[(size_t)(k + 1) * NOUT + col]);
    dst[u] = *reinterpret_cast<unsigned*>(&h);
}

// ---------------- LayerNorm stats: one warp per 256-wide row ----------------
__global__ void ln_stats_kernel(const float* __restrict__ x, int n) {
    int row  = blockIdx.x * 8 + (threadIdx.x >> 5);
    if (row >= n) return;
    int lane = threadIdx.x & 31;
    const float* xr = x + (size_t)row * IN_DIM;

    float4 v0 = *(const float4*)(xr + lane * 8);
    float4 v1 = *(const float4*)(xr + lane * 8 + 4);

    float s  = v0.x + v0.y + v0.z + v0.w + v1.x + v1.y + v1.z + v1.w;
    float sq = v0.x*v0.x + v0.y*v0.y + v0.z*v0.z + v0.w*v0.w
             + v1.x*v1.x + v1.y*v1.y + v1.z*v1.z + v1.w*v1.w;
    #pragma unroll
    for (int off = 16; off > 0; off >>= 1) {
        s  += __shfl_xor_sync(0xffffffffu, s,  off);
        sq += __shfl_xor_sync(0xffffffffu, sq, off);
    }
    if (lane == 0) {
        float mu  = s * (1.0f / IN_DIM);
        float var = sq * (1.0f / IN_DIM) - mu * mu;
        g_mu[row] = mu;
        g_rs[row] = rsqrtf(var + LN_EPS);
    }
}

// ---------------- degree / CSR build ----------------
__global__ void zero_deg_kernel(int n) {
    int i = blockIdx.x * blockDim.x + threadIdx.x;
    if (i < n) g_deg[i] = 0;
}

__global__ void count_kernel(const int* __restrict__ ei, int e, int n) {
    int i = blockIdx.x * blockDim.x + threadIdx.x;
    if (i >= e) return;
    int d = clampi(ei[e + i], 0, n - 1);
    atomicAdd(&g_deg[d], 1);
}

__global__ void dinv_kernel(int n) {
    int i = blockIdx.x * blockDim.x + threadIdx.x;
    if (i < n) g_dinv[i] = rsqrtf(1.0f + (float)g_deg[i]);
}

// ---------------- 3-phase multi-block exclusive scan of g_deg ----------------
// phase 1: per-block (256 elems) exclusive scan into g_rowptr; block sums out
__global__ void scan_blocks_kernel(int n) {
    __shared__ int ws[8];
    int i = blockIdx.x * 256 + threadIdx.x;
    int lane = threadIdx.x & 31, wid = threadIdx.x >> 5;
    int v = (i < n) ? g_deg[i] : 0;
    int x = v;
    #pragma unroll
    for (int off = 1; off < 32; off <<= 1) {
        int y = __shfl_up_sync(0xffffffffu, x, off);
        if (lane >= off) x += y;
    }
    if (lane == 31) ws[wid] = x;
    __syncthreads();
    if (wid == 0) {
        int w = (lane < 8) ? ws[lane] : 0;
        #pragma unroll
        for (int off = 1; off < 8; off <<= 1) {
            int y = __shfl_up_sync(0xffffffffu, w, off);
            if (lane >= off) w += y;
        }
        if (lane < 8) ws[lane] = w;
    }
    __syncthreads();
    int woff = wid ? ws[wid - 1] : 0;
    if (i < n) g_rowptr[i] = woff + x - v;        // block-local exclusive
    if (threadIdx.x == 255) g_bsum[blockIdx.x] = woff + x;
}

// phase 2: single block scans <=256 block sums (exclusive into g_boff)
__global__ void scan_sums_kernel(int nb, int n) {
    __shared__ int ws[8];
    int b = threadIdx.x;
    int lane = b & 31, wid = b >> 5;
    int v = (b < nb) ? g_bsum[b] : 0;
    int x = v;
    #pragma unroll
    for (int off = 1; off < 32; off <<= 1) {
        int y = __shfl_up_sync(0xffffffffu, x, off);
        if (lane >= off) x += y;
    }
    if (lane == 31) ws[wid] = x;
    __syncthreads();
    if (wid == 0) {
        int w = (lane < 8) ? ws[lane] : 0;
        #pragma unroll
        for (int off = 1; off < 8; off <<= 1) {
            int y = __shfl_up_sync(0xffffffffu, w, off);
            if (lane >= off) w += y;
        }
        if (lane < 8) ws[lane] = w;
    }
    __syncthreads();
    int woff = wid ? ws[wid - 1] : 0;
    g_boff[b] = woff + x - v;
    if (b == 255) g_rowptr[n] = woff + x;          // grand total
}

// phase 3: add block offsets, fill cursor
__global__ void scan_add_kernel(int n) {
    int i = blockIdx.x * 256 + threadIdx.x;
    if (i >= n) return;
    int rp = g_rowptr[i] + g_boff[i >> 8];
    g_rowptr[i] = rp;
    g_cursor[i] = rp;
}

__global__ void scatter_kernel(const int* __restrict__ ei, int e, int n) {
    int i = blockIdx.x * blockDim.x + threadIdx.x;
    if (i >= e) return;
    int s = clampi(ei[i],     0, n - 1);
    int d = clampi(ei[e + i], 0, n - 1);
    int pos = atomicAdd(&g_cursor[d], 1);
    g_cidx[pos] = s;
    g_w[pos] = g_dinv[s] * g_dinv[d];
}

// ---------------- fp16 tensor-core GEMM: g_th[M,NOUT] = A[M,K] @ W[K,NOUT] ---
// m16n8k16 fp16 MMA, fp32 accumulate. BM=64, BK=32, A double-buffered smem,
// B direct LDG.64 from pre-packed fragment-order W (L2-resident).
// LN=true: A = fp32 x with layernorm fused. LN=false: A = g_hh (fp16, raw copy).
template <int K, int NOUT, bool LN, int WSEL>
__launch_bounds__(256, 3)
__global__ void gemm_tc_kernel(const float* __restrict__ Ain,
                               const float* __restrict__ gamma,
                               const float* __restrict__ beta, int M) {
    const unsigned* __restrict__ Wp =
        (WSEL == 1) ? g_w1p : (WSEL == 2) ? g_w2p : g_w3p;
    __half* __restrict__ C = g_th;

    constexpr int BM  = 64;
    constexpr int NPW = NOUT / 2;
    constexpr int NT  = NPW / 8;
    constexpr int NTT = NOUT / 8;
    constexpr int ABLK  = 132;
    constexpr int TILES = K / 32;

    __shared__ alignas(16) unsigned Ah[2][8 * ABLK];

    int tid  = threadIdx.x;
    int wid  = tid >> 5;
    int lane = tid & 31;
    int qr   = lane >> 2;
    int qc   = lane & 3;
    int wr   = wid >> 1;
    int wc   = wid & 1;
    int m0   = blockIdx.x * BM;

    int kc     = (tid & 7) * 4;
    int kstepL = kc >> 4;
    int lsubA  = ((kc & 15) & 7) >> 1;
    int khalf  = ((kc & 15) & 8) ? 2 : 0;

    unsigned aps[2][2];
    float4 gm, bt;

    auto loadA = [&](int t) {
        int kt = t * 32;
        if (LN) {
            gm = *(const float4*)(gamma + kt + kc);
            bt = *(const float4*)(beta  + kt + kc);
        }
        #pragma unroll
        for (int p = 0; p < 2; p++) {
            int r  = (tid >> 3) + p * 32;
            int gr = m0 + r;
            if (LN) {
                float4 a = make_float4(0.f, 0.f, 0.f, 0.f);
                if (gr < M) {
                    a = *(const float4*)(Ain + (size_t)gr * K + kt + kc);
                    float mu = g_mu[gr], rs = g_rs[gr];
                    a.x = (a.x - mu) * rs * gm.x + bt.x;
                    a.y = (a.y - mu) * rs * gm.y + bt.y;
                    a.z = (a.z - mu) * rs * gm.z + bt.z;
                    a.w = (a.w - mu) * rs * gm.w + bt.w;
                }
                __half2 h01 = __floats2half2_rn(a.x, a.y);
                __half2 h23 = __floats2half2_rn(a.z, a.w);
                aps[p][0] = *reinterpret_cast<unsigned*>(&h01);
                aps[p][1] = *reinterpret_cast<unsigned*>(&h23);
            } else {
                uint2 raw = make_uint2(0u, 0u);
                if (gr < M)
                    raw = *(const uint2*)(g_hh + (size_t)gr * K + kt + kc);
                aps[p][0] = raw.x;
                aps[p][1] = raw.y;
            }
        }
    };
    auto storeA = [&](int buf) {
        #pragma unroll
        for (int p = 0; p < 2; p++) {
            int r   = (tid >> 3) + p * 32;
            int s_  = r >> 4;
            int rin = r & 15;
            int lzero = (rin & 7) * 4 + lsubA;
            int reg   = ((rin >> 3) & 1) + khalf;
            unsigned* base = &Ah[buf][(s_ * 2 + kstepL) * ABLK];
            base[lzero * 4 + reg]       = aps[p][0];
            base[(lzero + 1) * 4 + reg] = aps[p][1];
        }
    };

    float c[NT][4];
    #pragma unroll
    for (int ni = 0; ni < NT; ni++)
        #pragma unroll
        for (int j = 0; j < 4; j++) c[ni][j] = 0.0f;

    loadA(0);
    storeA(0);
    __syncthreads();

    for (int t = 0; t < TILES; t++) {
        uint2 bf[2][NT];
        #pragma unroll
        for (int ks = 0; ks < 2; ks++)
            #pragma unroll
            for (int ni = 0; ni < NT; ni++)
                bf[ks][ni] = __ldg((const uint2*)(Wp +
                    (((t * 2 + ks) * NTT + wc * NT + ni) * 64 + lane * 2)));

        if (t + 1 < TILES) loadA(t + 1);

        #pragma unroll
        for (int ks = 0; ks < 2; ks++) {
            uint4 af = *(const uint4*)&Ah[t & 1][(wr * 2 + ks) * ABLK + lane * 4];
            #pragma unroll
            for (int ni = 0; ni < NT; ni++) {
                asm volatile(
                    "mma.sync.aligned.m16n8k16.row.col.f32.f16.f16.f32 "
                    "{%0,%1,%2,%3}, {%4,%5,%6,%7}, {%8,%9}, {%0,%1,%2,%3};"
                    : "+f"(c[ni][0]), "+f"(c[ni][1]),
                      "+f"(c[ni][2]), "+f"(c[ni][3])
                    : "r"(af.x), "r"(af.y), "r"(af.z), "r"(af.w),
                      "r"(bf[ks][ni].x), "r"(bf[ks][ni].y));
            }
        }

        if (t + 1 < TILES) storeA((t + 1) & 1);
        __syncthreads();
    }

    int row = m0 + wr * 16 + qr;
    #pragma unroll
    for (int ni = 0; ni < NT; ni++) {
        int col = wc * NPW + ni * 8 + 2 * qc;
        if (row < M) {
            *(__half2*)(C + (size_t)row * NOUT + col) =
                __floats2half2_rn(c[ni][0], c[ni][1]);
        }
        if (row + 8 < M) {
            *(__half2*)(C + (size_t)(row + 8) * NOUT + col) =
                __floats2half2_rn(c[ni][2], c[ni][3]);
        }
    }
}

// ---------------- aggregation: out[v] = sum_{(s->v)} t[s]*w + t[v]*dinv[v]^2 + b
// Reads g_th (fp16), fp32 accumulate. TO_TMP: writes g_hh (fp16); else fp32 outp.
template <int D, bool RELU, bool TO_TMP>
__global__ void agg_kernel(const float* __restrict__ bias,
                           float* __restrict__ outp, int n) {
    const __half* __restrict__ t = g_th;
    constexpr int GS  = D / 4;
    constexpr int GPB = 128 / GS;
    int g = blockIdx.x * GPB + threadIdx.x / GS;
    if (g >= n) return;
    int lane = threadIdx.x % GS;
    int c = lane * 4;

    float dv = g_dinv[g];
    float sc = dv * dv;
    float4 b4 = *(const float4*)(bias + c);

    __half2 sv0, sv1;
    {
        uint2 raw = *(const uint2*)(t + (size_t)g * D + c);
        sv0 = *reinterpret_cast<__half2*>(&raw.x);
        sv1 = *reinterpret_cast<__half2*>(&raw.y);
    }
    float2 f0 = __half22float2(sv0);
    float2 f1 = __half22float2(sv1);
    float4 acc;
    acc.x = f0.x * sc + b4.x;
    acc.y = f0.y * sc + b4.y;
    acc.z = f1.x * sc + b4.z;
    acc.w = f1.y * sc + b4.w;

    int e0 = g_rowptr[g], e1 = g_rowptr[g + 1];
    for (int e = e0; e < e1; e++) {
        int s   = g_cidx[e];
        float w = g_w[e];
        uint2 raw = *(const uint2*)(t + (size_t)s * D + c);
        float2 h0 = __half22float2(*reinterpret_cast<__half2*>(&raw.x));
        float2 h1 = __half22float2(*reinterpret_cast<__half2*>(&raw.y));
        acc.x += h0.x * w;
        acc.y += h0.y * w;
        acc.z += h1.x * w;
        acc.w += h1.y * w;
    }
    if (RELU) {
        acc.x = fmaxf(acc.x, 0.f);
        acc.y = fmaxf(acc.y, 0.f);
        acc.z = fmaxf(acc.z, 0.f);
        acc.w = fmaxf(acc.w, 0.f);
    }
    if (TO_TMP) {
        __half2 o0 = __floats2half2_rn(acc.x, acc.y);
        __half2 o1 = __floats2half2_rn(acc.z, acc.w);
        uint2 packed = make_uint2(*reinterpret_cast<unsigned*>(&o0),
                                  *reinterpret_cast<unsigned*>(&o1));
        *(uint2*)(g_hh + (size_t)g * D + c) = packed;
    } else {
        *(float4*)(outp + (size_t)g * D + c) = acc;
    }
}

// ---------------- launch ----------------
extern "C" void kernel_launch(void* const* d_in, const int* in_sizes, int n_in,
                              void* d_out, int out_size) {
    const float* x     = (const float*)d_in[0];
    const int*   ei    = (const int*)d_in[1];
    const float* gamma = (const float*)d_in[2];
    const float* beta  = (const float*)d_in[3];
    const float* W1    = (const float*)d_in[4];
    const float* b1    = (const float*)d_in[5];
    const float* W2    = (const float*)d_in[6];
    const float* b2    = (const float*)d_in[7];
    const float* W3    = (const float*)d_in[8];
    const float* b3    = (const float*)d_in[9];
    float* out = (float*)d_out;

    int n  = in_sizes[0] / IN_DIM;
    int e  = in_sizes[1] / 2;
    int nb = (n + 255) / 256;

    wpack_kernel<IN_DIM, HID, 1><<<(16384 + 255) / 256, 256>>>(W1);
    ln_stats_kernel<<<(n + 7) / 8, 256>>>(x, n);
    zero_deg_kernel<<<(n + 255) / 256, 256>>>(n);

    gemm_tc_kernel<IN_DIM, HID, true, 1><<<(n + 63) / 64, 256>>>(x, gamma, beta, n);

    count_kernel<<<(e + 255) / 256, 256>>>(ei, e, n);
    wpack_kernel<HID, HID, 2><<<(8192 + 255) / 256, 256>>>(W2);
    wpack_kernel<HID, ZDIM, 3><<<(4096 + 255) / 256, 256>>>(W3);
    dinv_kernel<<<(n + 255) / 256, 256>>>(n);

    scan_blocks_kernel<<<nb, 256>>>(n);
    scan_sums_kernel<<<1, 256>>>(nb, n);
    scan_add_kernel<<<nb, 256>>>(n);

    scatter_kernel<<<(e + 255) / 256, 256>>>(ei, e, n);

    agg_kernel<HID, true, true><<<(n + 3) / 4, 128>>>(b1, nullptr, n);

    gemm_tc_kernel<HID, HID, false, 2><<<(n + 63) / 64, 256>>>(nullptr, nullptr, nullptr, n);
    agg_kernel<HID, true, true><<<(n + 3) / 4, 128>>>(b2, nullptr, n);

    gemm_tc_kernel<HID, ZDIM, false, 3><<<(n + 63) / 64, 256>>>(nullptr, nullptr, nullptr, n);
    agg_kernel<ZDIM, false, false><<<(n + 7) / 8, 128>>>(b3, out, n);
}

// round 14
// speedup vs baseline: 1.5131x; 1.1192x over previous
#include <cuda_runtime.h>
#include <cuda_bf16.h>
#include <cuda_fp16.h>
#include <cstddef>

#define NMAX   50000
#define EMAX   800000
#define IN_DIM 256
#define HID    128
#define ZDIM   64
#define LN_EPS 1e-5f

// ---------------- device scratch (static, no allocation) ----------------
__device__ __half   g_xh[(size_t)NMAX * IN_DIM]; // layernormed input, fp16
__device__ __half   g_th[(size_t)NMAX * HID];    // GEMM output, fp16
__device__ __half   g_hh[(size_t)NMAX * HID];    // layer output after agg+relu, fp16
__device__ float    g_dinv[NMAX];
__device__ float    g_w  [EMAX];                 // per-edge coef dinv[s]*dinv[d]
__device__ int      g_deg[NMAX];
__device__ int      g_rowptr[NMAX + 1];
__device__ int      g_cursor[NMAX];
__device__ int      g_cidx[EMAX];                // src indices sorted by dst
__device__ int      g_bsum[256];
__device__ int      g_boff[256];
// pre-packed W in mma B-fragment order (uint = half2)
__device__ unsigned g_w1p[(IN_DIM/16) * (HID/8)  * 64];  // 16384
__device__ unsigned g_w2p[(HID/16)    * (HID/8)  * 64];  // 8192
__device__ unsigned g_w3p[(HID/16)    * (ZDIM/8) * 64];  // 4096

__device__ __forceinline__ int clampi(int v, int lo, int hi) {
    return min(max(v, lo), hi);
}

#define CP_ASYNC16(dst, src) \
    asm volatile("cp.async.ca.shared.global [%0], [%1], 16;" \
                 :: "r"(dst), "l"(src))
#define CP_COMMIT() asm volatile("cp.async.commit_group;" ::: "memory")
#define CP_WAIT3()  asm volatile("cp.async.wait_group 3;"  ::: "memory")

__device__ __forceinline__ unsigned smem_u32(const void* p) {
    unsigned a;
    asm("{ .reg .u64 t; cvta.to.shared.u64 t, %1; cvt.u32.u64 %0, t; }"
        : "=r"(a) : "l"(p));
    return a;
}

// ---------------- W pre-pack: fragment order for m16n8k16 B operand --------
template <int K, int NOUT, int SEL>
__global__ void wpack_kernel(const float* __restrict__ W) {
    unsigned* dst = (SEL == 1) ? g_w1p : (SEL == 2) ? g_w2p : g_w3p;
    constexpr int NTT = NOUT / 8;
    constexpr int TOT = (K / 16) * NTT * 64;
    int u = blockIdx.x * blockDim.x + threadIdx.x;
    if (u >= TOT) return;
    int reg  = u & 1;
    int lane = (u >> 1) & 31;
    int rest = u >> 6;
    int ni   = rest % NTT;
    int ksg  = rest / NTT;
    int col  = ni * 8 + (lane >> 2);
    int k    = ksg * 16 + (lane & 3) * 2 + reg * 8;
    __half2 h = __floats2half2_rn(W[(size_t)k * NOUT + col],
                                  W[(size_t)(k + 1) * NOUT + col]);
    dst[u] = *reinterpret_cast<unsigned*>(&h);
}

// ---------------- one-pass LayerNorm -> fp16: one warp per 256-wide row ----
__global__ void ln_apply_kernel(const float* __restrict__ x,
                                const float* __restrict__ gamma,
                                const float* __restrict__ beta, int n) {
    int row  = blockIdx.x * 8 + (threadIdx.x >> 5);
    if (row >= n) return;
    int lane = threadIdx.x & 31;
    const float* xr = x + (size_t)row * IN_DIM;

    float4 v0 = *(const float4*)(xr + lane * 8);
    float4 v1 = *(const float4*)(xr + lane * 8 + 4);

    float s  = v0.x + v0.y + v0.z + v0.w + v1.x + v1.y + v1.z + v1.w;
    float sq = v0.x*v0.x + v0.y*v0.y + v0.z*v0.z + v0.w*v0.w
             + v1.x*v1.x + v1.y*v1.y + v1.z*v1.z + v1.w*v1.w;
    #pragma unroll
    for (int off = 16; off > 0; off >>= 1) {
        s  += __shfl_xor_sync(0xffffffffu, s,  off);
        sq += __shfl_xor_sync(0xffffffffu, sq, off);
    }
    float mu  = s * (1.0f / IN_DIM);
    float var = sq * (1.0f / IN_DIM) - mu * mu;
    float rs  = rsqrtf(var + LN_EPS);

    float4 g0 = *(const float4*)(gamma + lane * 8);
    float4 g1 = *(const float4*)(gamma + lane * 8 + 4);
    float4 b0 = *(const float4*)(beta + lane * 8);
    float4 b1 = *(const float4*)(beta + lane * 8 + 4);

    __half2 o[4];
    o[0] = __floats2half2_rn((v0.x - mu) * rs * g0.x + b0.x,
                             (v0.y - mu) * rs * g0.y + b0.y);
    o[1] = __floats2half2_rn((v0.z - mu) * rs * g0.z + b0.z,
                             (v0.w - mu) * rs * g0.w + b0.w);
    o[2] = __floats2half2_rn((v1.x - mu) * rs * g1.x + b1.x,
                             (v1.y - mu) * rs * g1.y + b1.y);
    o[3] = __floats2half2_rn((v1.z - mu) * rs * g1.z + b1.z,
                             (v1.w - mu) * rs * g1.w + b1.w);
    *(uint4*)(g_xh + (size_t)row * IN_DIM + lane * 8) =
        *reinterpret_cast<uint4*>(o);
}

// ---------------- degree / CSR build ----------------
__global__ void zero_deg_kernel(int n) {
    int i = blockIdx.x * blockDim.x + threadIdx.x;
    if (i < n) g_deg[i] = 0;
}

__global__ void count_kernel(const int* __restrict__ ei, int e, int n) {
    int i = blockIdx.x * blockDim.x + threadIdx.x;
    if (i >= e) return;
    int d = clampi(ei[e + i], 0, n - 1);
    atomicAdd(&g_deg[d], 1);
}

__global__ void dinv_kernel(int n) {
    int i = blockIdx.x * blockDim.x + threadIdx.x;
    if (i < n) g_dinv[i] = rsqrtf(1.0f + (float)g_deg[i]);
}

// ---------------- 3-phase multi-block exclusive scan of g_deg ----------------
__global__ void scan_blocks_kernel(int n) {
    __shared__ int ws[8];
    int i = blockIdx.x * 256 + threadIdx.x;
    int lane = threadIdx.x & 31, wid = threadIdx.x >> 5;
    int v = (i < n) ? g_deg[i] : 0;
    int x = v;
    #pragma unroll
    for (int off = 1; off < 32; off <<= 1) {
        int y = __shfl_up_sync(0xffffffffu, x, off);
        if (lane >= off) x += y;
    }
    if (lane == 31) ws[wid] = x;
    __syncthreads();
    if (wid == 0) {
        int w = (lane < 8) ? ws[lane] : 0;
        #pragma unroll
        for (int off = 1; off < 8; off <<= 1) {
            int y = __shfl_up_sync(0xffffffffu, w, off);
            if (lane >= off) w += y;
        }
        if (lane < 8) ws[lane] = w;
    }
    __syncthreads();
    int woff = wid ? ws[wid - 1] : 0;
    if (i < n) g_rowptr[i] = woff + x - v;
    if (threadIdx.x == 255) g_bsum[blockIdx.x] = woff + x;
}

__global__ void scan_sums_kernel(int nb, int n) {
    __shared__ int ws[8];
    int b = threadIdx.x;
    int lane = b & 31, wid = b >> 5;
    int v = (b < nb) ? g_bsum[b] : 0;
    int x = v;
    #pragma unroll
    for (int off = 1; off < 32; off <<= 1) {
        int y = __shfl_up_sync(0xffffffffu, x, off);
        if (lane >= off) x += y;
    }
    if (lane == 31) ws[wid] = x;
    __syncthreads();
    if (wid == 0) {
        int w = (lane < 8) ? ws[lane] : 0;
        #pragma unroll
        for (int off = 1; off < 8; off <<= 1) {
            int y = __shfl_up_sync(0xffffffffu, w, off);
            if (lane >= off) w += y;
        }
        if (lane < 8) ws[lane] = w;
    }
    __syncthreads();
    int woff = wid ? ws[wid - 1] : 0;
    g_boff[b] = woff + x - v;
    if (b == 255) g_rowptr[n] = woff + x;
}

__global__ void scan_add_kernel(int n) {
    int i = blockIdx.x * 256 + threadIdx.x;
    if (i >= n) return;
    int rp = g_rowptr[i] + g_boff[i >> 8];
    g_rowptr[i] = rp;
    g_cursor[i] = rp;
}

__global__ void scatter_kernel(const int* __restrict__ ei, int e, int n) {
    int i = blockIdx.x * blockDim.x + threadIdx.x;
    if (i >= e) return;
    int s = clampi(ei[i],     0, n - 1);
    int d = clampi(ei[e + i], 0, n - 1);
    int pos = atomicAdd(&g_cursor[d], 1);
    g_cidx[pos] = s;
    g_w[pos] = g_dinv[s] * g_dinv[d];
}

// ---------------- fp16 GEMM: g_th[M,NOUT] = A[M,K] @ W[K,NOUT] ---------------
// A: fp16 row-major (g_xh or g_hh), 4-stage cp.async pipeline + ldmatrix.x4.
// B: direct LDG.64 from pre-packed fragment-order W (L2-resident).
// 8 warps = 4 m16 strips x 2 col halves. BM=64, BK=32.
template <int K, int NOUT, int ASEL, int WSEL>
__launch_bounds__(256, 3)
__global__ void gemm_tc_kernel(int M) {
    const __half* __restrict__ A = (ASEL == 0) ? g_xh : g_hh;
    const unsigned* __restrict__ Wp =
        (WSEL == 1) ? g_w1p : (WSEL == 2) ? g_w2p : g_w3p;
    __half* __restrict__ C = g_th;

    constexpr int BM   = 64;
    constexpr int NPW  = NOUT / 2;
    constexpr int NT   = NPW / 8;
    constexpr int NTT  = NOUT / 8;
    constexpr int SROW = 40;             // halves per smem row (32 + 8 pad)
    constexpr int STG  = BM * SROW;      // halves per stage
    constexpr int TILES = K / 32;

    __shared__ alignas(16) __half Asm[4 * STG];

    int tid  = threadIdx.x;
    int wid  = tid >> 5;
    int lane = tid & 31;
    int qr   = lane >> 2;
    int qc   = lane & 3;
    int wr   = wid >> 1;      // m16 strip
    int wc   = wid & 1;       // col half
    int m0   = blockIdx.x * BM;

    unsigned sbase = smem_u32(Asm);

    // cp.async issue: 64 rows x 4 chunks of 16B (32 halves per row)
    int lrow = tid >> 2;
    int lch  = tid & 3;
    int gr   = min(m0 + lrow, M - 1);
    const __half* gsrc_row = A + (size_t)gr * K + lch * 8;
    unsigned sdst_row = sbase + (unsigned)((lrow * SROW + lch * 8) * 2);

    auto issueA = [&](int t) {
        CP_ASYNC16(sdst_row + (unsigned)((t & 3) * STG * 2),
                   gsrc_row + t * 32);
    };

    float c[NT][4];
    #pragma unroll
    for (int ni = 0; ni < NT; ni++)
        #pragma unroll
        for (int j = 0; j < 4; j++) c[ni][j] = 0.0f;

    // prologue: fill 4 stages (TILES >= 4 for all our shapes)
    #pragma unroll
    for (int s = 0; s < 4; s++) {
        issueA(s);
        CP_COMMIT();
    }

    // ldmatrix lane address: row wr*16 + (lane&15), col halves (lane>>4)*8
    unsigned lm_base = sbase +
        (unsigned)(((wr * 16 + (lane & 15)) * SROW + (lane >> 4) * 8) * 2);

    for (int t = 0; t < TILES; t++) {
        CP_WAIT3();
        __syncthreads();

        unsigned stg_off = (unsigned)((t & 3) * STG * 2);
        #pragma unroll
        for (int ks = 0; ks < 2; ks++) {
            unsigned a0, a1, a2, a3;
            asm volatile(
                "ldmatrix.sync.aligned.m8n8.x4.shared.b16 {%0,%1,%2,%3}, [%4];"
                : "=r"(a0), "=r"(a1), "=r"(a2), "=r"(a3)
                : "r"(lm_base + stg_off + (unsigned)(ks * 32)));
            uint2 bf[NT];
            #pragma unroll
            for (int ni = 0; ni < NT; ni++)
                bf[ni] = __ldg((const uint2*)(Wp +
                    (((t * 2 + ks) * NTT + wc * NT + ni) * 64 + lane * 2)));
            #pragma unroll
            for (int ni = 0; ni < NT; ni++) {
                asm volatile(
                    "mma.sync.aligned.m16n8k16.row.col.f32.f16.f16.f32 "
                    "{%0,%1,%2,%3}, {%4,%5,%6,%7}, {%8,%9}, {%0,%1,%2,%3};"
                    : "+f"(c[ni][0]), "+f"(c[ni][1]),
                      "+f"(c[ni][2]), "+f"(c[ni][3])
                    : "r"(a0), "r"(a1), "r"(a2), "r"(a3),
                      "r"(bf[ni].x), "r"(bf[ni].y));
            }
        }

        __syncthreads();          // all warps done reading stage t&3
        if (t + 4 < TILES) issueA(t + 4);
        CP_COMMIT();              // empty group at tail keeps wait count exact
    }

    int row = m0 + wr * 16 + qr;
    #pragma unroll
    for (int ni = 0; ni < NT; ni++) {
        int col = wc * NPW + ni * 8 + 2 * qc;
        if (row < M) {
            *(__half2*)(C + (size_t)row * NOUT + col) =
                __floats2half2_rn(c[ni][0], c[ni][1]);
        }
        if (row + 8 < M) {
            *(__half2*)(C + (size_t)(row + 8) * NOUT + col) =
                __floats2half2_rn(c[ni][2], c[ni][3]);
        }
    }
}

// ---------------- aggregation: out[v] = sum_{(s->v)} t[s]*w + t[v]*dinv[v]^2 + b
// Reads g_th (fp16), fp32 accumulate. TO_TMP: writes g_hh (fp16); else fp32 outp.
template <int D, bool RELU, bool TO_TMP>
__global__ void agg_kernel(const float* __restrict__ bias,
                           float* __restrict__ outp, int n) {
    const __half* __restrict__ t = g_th;
    constexpr int GS  = D / 4;
    constexpr int GPB = 128 / GS;
    int g = blockIdx.x * GPB + threadIdx.x / GS;
    if (g >= n) return;
    int lane = threadIdx.x % GS;
    int c = lane * 4;

    float dv = g_dinv[g];
    float sc = dv * dv;
    float4 b4 = *(const float4*)(bias + c);

    __half2 sv0, sv1;
    {
        uint2 raw = *(const uint2*)(t + (size_t)g * D + c);
        sv0 = *reinterpret_cast<__half2*>(&raw.x);
        sv1 = *reinterpret_cast<__half2*>(&raw.y);
    }
    float2 f0 = __half22float2(sv0);
    float2 f1 = __half22float2(sv1);
    float4 acc;
    acc.x = f0.x * sc + b4.x;
    acc.y = f0.y * sc + b4.y;
    acc.z = f1.x * sc + b4.z;
    acc.w = f1.y * sc + b4.w;

    int e0 = g_rowptr[g], e1 = g_rowptr[g + 1];
    for (int e = e0; e < e1; e++) {
        int s   = g_cidx[e];
        float w = g_w[e];
        uint2 raw = *(const uint2*)(t + (size_t)s * D + c);
        float2 h0 = __half22float2(*reinterpret_cast<__half2*>(&raw.x));
        float2 h1 = __half22float2(*reinterpret_cast<__half2*>(&raw.y));
        acc.x += h0.x * w;
        acc.y += h0.y * w;
        acc.z += h1.x * w;
        acc.w += h1.y * w;
    }
    if (RELU) {
        acc.x = fmaxf(acc.x, 0.f);
        acc.y = fmaxf(acc.y, 0.f);
        acc.z = fmaxf(acc.z, 0.f);
        acc.w = fmaxf(acc.w, 0.f);
    }
    if (TO_TMP) {
        __half2 o0 = __floats2half2_rn(acc.x, acc.y);
        __half2 o1 = __floats2half2_rn(acc.z, acc.w);
        uint2 packed = make_uint2(*reinterpret_cast<unsigned*>(&o0),
                                  *reinterpret_cast<unsigned*>(&o1));
        *(uint2*)(g_hh + (size_t)g * D + c) = packed;
    } else {
        *(float4*)(outp + (size_t)g * D + c) = acc;
    }
}

// ---------------- launch ----------------
extern "C" void kernel_launch(void* const* d_in, const int* in_sizes, int n_in,
                              void* d_out, int out_size) {
    const float* x     = (const float*)d_in[0];
    const int*   ei    = (const int*)d_in[1];
    const float* gamma = (const float*)d_in[2];
    const float* beta  = (const float*)d_in[3];
    const float* W1    = (const float*)d_in[4];
    const float* b1    = (const float*)d_in[5];
    const float* W2    = (const float*)d_in[6];
    const float* b2    = (const float*)d_in[7];
    const float* W3    = (const float*)d_in[8];
    const float* b3    = (const float*)d_in[9];
    float* out = (float*)d_out;

    int n  = in_sizes[0] / IN_DIM;
    int e  = in_sizes[1] / 2;
    int nb = (n + 255) / 256;

    wpack_kernel<IN_DIM, HID, 1><<<(16384 + 255) / 256, 256>>>(W1);
    ln_apply_kernel<<<(n + 7) / 8, 256>>>(x, gamma, beta, n);
    zero_deg_kernel<<<(n + 255) / 256, 256>>>(n);

    gemm_tc_kernel<IN_DIM, HID, 0, 1><<<(n + 63) / 64, 256>>>(n);

    count_kernel<<<(e + 255) / 256, 256>>>(ei, e, n);
    wpack_kernel<HID, HID, 2><<<(8192 + 255) / 256, 256>>>(W2);
    wpack_kernel<HID, ZDIM, 3><<<(4096 + 255) / 256, 256>>>(W3);
    dinv_kernel<<<(n + 255) / 256, 256>>>(n);

    scan_blocks_kernel<<<nb, 256>>>(n);
    scan_sums_kernel<<<1, 256>>>(nb, n);
    scan_add_kernel<<<nb, 256>>>(n);

    scatter_kernel<<<(e + 255) / 256, 256>>>(ei, e, n);

    agg_kernel<HID, true, true><<<(n + 3) / 4, 128>>>(b1, nullptr, n);

    gemm_tc_kernel<HID, HID, 1, 2><<<(n + 63) / 64, 256>>>(n);
    agg_kernel<HID, true, true><<<(n + 3) / 4, 128>>>(b2, nullptr, n);

    gemm_tc_kernel<HID, ZDIM, 1, 3><<<(n + 63) / 64, 256>>>(n);
    agg_kernel<ZDIM, false, false><<<(n + 7) / 8, 128>>>(b3, out, n);
}

// round 15
// speedup vs baseline: 1.5345x; 1.0141x over previous
#include <cuda_runtime.h>
#include <cuda_bf16.h>
#include <cuda_fp16.h>
#include <cstddef>

#define NMAX   50000
#define EMAX   800000
#define IN_DIM 256
#define HID    128
#define ZDIM   64
#define LN_EPS 1e-5f

// ---------------- device scratch (static, no allocation) ----------------
__device__ __half   g_xh[(size_t)NMAX * IN_DIM]; // layernormed input, fp16
__device__ __half   g_th[(size_t)NMAX * HID];    // GEMM output, fp16
__device__ __half   g_hh[(size_t)NMAX * HID];    // layer output after agg+relu, fp16
__device__ float    g_dinv[NMAX];
__device__ float    g_w  [EMAX];                 // per-edge coef dinv[s]*dinv[d]
__device__ int      g_deg[NMAX];
__device__ int      g_rowptr[NMAX + 1];
__device__ int      g_cursor[NMAX];
__device__ int      g_cidx[EMAX];                // src indices sorted by dst
__device__ int      g_bsum[256];
__device__ int      g_boff[256];
// pre-packed W in mma B-fragment order (uint = half2)
__device__ unsigned g_w1p[(IN_DIM/16) * (HID/8)  * 64];  // 16384
__device__ unsigned g_w2p[(HID/16)    * (HID/8)  * 64];  // 8192
__device__ unsigned g_w3p[(HID/16)    * (ZDIM/8) * 64];  // 4096

__device__ __forceinline__ int clampi(int v, int lo, int hi) {
    return min(max(v, lo), hi);
}

#define CP_ASYNC16(dst, src) \
    asm volatile("cp.async.ca.shared.global [%0], [%1], 16;" \
                 :: "r"(dst), "l"(src))
#define CP_COMMIT() asm volatile("cp.async.commit_group;" ::: "memory")
#define CP_WAIT2()  asm volatile("cp.async.wait_group 2;"  ::: "memory")

__device__ __forceinline__ unsigned smem_u32(const void* p) {
    unsigned a;
    asm("{ .reg .u64 t; cvta.to.shared.u64 t, %1; cvt.u32.u64 %0, t; }"
        : "=r"(a) : "l"(p));
    return a;
}

// ---------------- W pre-pack: fragment order for m16n8k16 B operand --------
template <int K, int NOUT>
__device__ __forceinline__ void wpack_one(unsigned* dst,
                                          const float* __restrict__ W, int u) {
    constexpr int NTT = NOUT / 8;
    int reg  = u & 1;
    int lane = (u >> 1) & 31;
    int rest = u >> 6;
    int ni   = rest % NTT;
    int ksg  = rest / NTT;
    int col  = ni * 8 + (lane >> 2);
    int k    = ksg * 16 + (lane & 3) * 2 + reg * 8;
    __half2 h = __floats2half2_rn(W[(size_t)k * NOUT + col],
                                  W[(size_t)(k + 1) * NOUT + col]);
    dst[u] = *reinterpret_cast<unsigned*>(&h);
}

__global__ void wpack_all_kernel(const float* __restrict__ W1,
                                 const float* __restrict__ W2,
                                 const float* __restrict__ W3) {
    int u = blockIdx.x * 256 + threadIdx.x;
    if (u < 16384) {
        wpack_one<IN_DIM, HID>(g_w1p, W1, u);
    } else if (u < 16384 + 8192) {
        wpack_one<HID, HID>(g_w2p, W2, u - 16384);
    } else if (u < 16384 + 8192 + 4096) {
        wpack_one<HID, ZDIM>(g_w3p, W3, u - (16384 + 8192));
    }
}

// ---------------- one-pass LayerNorm -> fp16: one warp per 256-wide row ----
__global__ void ln_apply_kernel(const float* __restrict__ x,
                                const float* __restrict__ gamma,
                                const float* __restrict__ beta, int n) {
    int row  = blockIdx.x * 8 + (threadIdx.x >> 5);
    if (row >= n) return;
    int lane = threadIdx.x & 31;
    const float* xr = x + (size_t)row * IN_DIM;

    float4 v0 = *(const float4*)(xr + lane * 8);
    float4 v1 = *(const float4*)(xr + lane * 8 + 4);

    float s  = v0.x + v0.y + v0.z + v0.w + v1.x + v1.y + v1.z + v1.w;
    float sq = v0.x*v0.x + v0.y*v0.y + v0.z*v0.z + v0.w*v0.w
             + v1.x*v1.x + v1.y*v1.y + v1.z*v1.z + v1.w*v1.w;
    #pragma unroll
    for (int off = 16; off > 0; off >>= 1) {
        s  += __shfl_xor_sync(0xffffffffu, s,  off);
        sq += __shfl_xor_sync(0xffffffffu, sq, off);
    }
    float mu  = s * (1.0f / IN_DIM);
    float var = sq * (1.0f / IN_DIM) - mu * mu;
    float rs  = rsqrtf(var + LN_EPS);

    float4 g0 = *(const float4*)(gamma + lane * 8);
    float4 g1 = *(const float4*)(gamma + lane * 8 + 4);
    float4 b0 = *(const float4*)(beta + lane * 8);
    float4 b1 = *(const float4*)(beta + lane * 8 + 4);

    __half2 o[4];
    o[0] = __floats2half2_rn((v0.x - mu) * rs * g0.x + b0.x,
                             (v0.y - mu) * rs * g0.y + b0.y);
    o[1] = __floats2half2_rn((v0.z - mu) * rs * g0.z + b0.z,
                             (v0.w - mu) * rs * g0.w + b0.w);
    o[2] = __floats2half2_rn((v1.x - mu) * rs * g1.x + b1.x,
                             (v1.y - mu) * rs * g1.y + b1.y);
    o[3] = __floats2half2_rn((v1.z - mu) * rs * g1.z + b1.z,
                             (v1.w - mu) * rs * g1.w + b1.w);
    *(uint4*)(g_xh + (size_t)row * IN_DIM + lane * 8) =
        *reinterpret_cast<uint4*>(o);
}

// ---------------- degree / CSR build ----------------
__global__ void zero_deg_kernel(int n) {
    int i = blockIdx.x * blockDim.x + threadIdx.x;
    if (i < n) g_deg[i] = 0;
}

__global__ void count_kernel(const int* __restrict__ ei, int e, int n) {
    int i = blockIdx.x * blockDim.x + threadIdx.x;
    if (i >= e) return;
    int d = clampi(ei[e + i], 0, n - 1);
    atomicAdd(&g_deg[d], 1);
}

// ---------------- 3-phase multi-block exclusive scan of g_deg ----------------
// phase 1 also computes g_dinv (fused).
__global__ void scan_blocks_kernel(int n) {
    __shared__ int ws[8];
    int i = blockIdx.x * 256 + threadIdx.x;
    int lane = threadIdx.x & 31, wid = threadIdx.x >> 5;
    int v = (i < n) ? g_deg[i] : 0;
    if (i < n) g_dinv[i] = rsqrtf(1.0f + (float)v);
    int x = v;
    #pragma unroll
    for (int off = 1; off < 32; off <<= 1) {
        int y = __shfl_up_sync(0xffffffffu, x, off);
        if (lane >= off) x += y;
    }
    if (lane == 31) ws[wid] = x;
    __syncthreads();
    if (wid == 0) {
        int w = (lane < 8) ? ws[lane] : 0;
        #pragma unroll
        for (int off = 1; off < 8; off <<= 1) {
            int y = __shfl_up_sync(0xffffffffu, w, off);
            if (lane >= off) w += y;
        }
        if (lane < 8) ws[lane] = w;
    }
    __syncthreads();
    int woff = wid ? ws[wid - 1] : 0;
    if (i < n) g_rowptr[i] = woff + x - v;
    if (threadIdx.x == 255) g_bsum[blockIdx.x] = woff + x;
}

__global__ void scan_sums_kernel(int nb, int n) {
    __shared__ int ws[8];
    int b = threadIdx.x;
    int lane = b & 31, wid = b >> 5;
    int v = (b < nb) ? g_bsum[b] : 0;
    int x = v;
    #pragma unroll
    for (int off = 1; off < 32; off <<= 1) {
        int y = __shfl_up_sync(0xffffffffu, x, off);
        if (lane >= off) x += y;
    }
    if (lane == 31) ws[wid] = x;
    __syncthreads();
    if (wid == 0) {
        int w = (lane < 8) ? ws[lane] : 0;
        #pragma unroll
        for (int off = 1; off < 8; off <<= 1) {
            int y = __shfl_up_sync(0xffffffffu, w, off);
            if (lane >= off) w += y;
        }
        if (lane < 8) ws[lane] = w;
    }
    __syncthreads();
    int woff = wid ? ws[wid - 1] : 0;
    g_boff[b] = woff + x - v;
    if (b == 255) g_rowptr[n] = woff + x;
}

__global__ void scan_add_kernel(int n) {
    int i = blockIdx.x * 256 + threadIdx.x;
    if (i >= n) return;
    int rp = g_rowptr[i] + g_boff[i >> 8];
    g_rowptr[i] = rp;
    g_cursor[i] = rp;
}

__global__ void scatter_kernel(const int* __restrict__ ei, int e, int n) {
    int i = blockIdx.x * blockDim.x + threadIdx.x;
    if (i >= e) return;
    int s = clampi(ei[i],     0, n - 1);
    int d = clampi(ei[e + i], 0, n - 1);
    int pos = atomicAdd(&g_cursor[d], 1);
    g_cidx[pos] = s;
    g_w[pos] = g_dinv[s] * g_dinv[d];
}

// ---------------- fp16 GEMM: g_th[M,NOUT] = A[M,K] @ W[K,NOUT] ---------------
// A: fp16 row-major (g_xh or g_hh), cp.async pipeline (4 buffers, 3 in flight)
// with ONE __syncthreads per tile (issue t+3 right after the barrier).
// B: direct LDG.64 from pre-packed fragment-order W (L2-resident).
// 8 warps = 4 m16 strips x 2 col halves. BM=64, BK=32.
template <int K, int NOUT, int ASEL, int WSEL>
__launch_bounds__(256, 3)
__global__ void gemm_tc_kernel(int M) {
    const __half* __restrict__ A = (ASEL == 0) ? g_xh : g_hh;
    const unsigned* __restrict__ Wp =
        (WSEL == 1) ? g_w1p : (WSEL == 2) ? g_w2p : g_w3p;
    __half* __restrict__ C = g_th;

    constexpr int BM   = 64;
    constexpr int NPW  = NOUT / 2;
    constexpr int NT   = NPW / 8;
    constexpr int NTT  = NOUT / 8;
    constexpr int SROW = 40;             // halves per smem row (32 + 8 pad)
    constexpr int STG  = BM * SROW;      // halves per stage
    constexpr int TILES = K / 32;

    __shared__ alignas(16) __half Asm[4 * STG];

    int tid  = threadIdx.x;
    int wid  = tid >> 5;
    int lane = tid & 31;
    int qr   = lane >> 2;
    int qc   = lane & 3;
    int wr   = wid >> 1;      // m16 strip
    int wc   = wid & 1;       // col half
    int m0   = blockIdx.x * BM;

    unsigned sbase = smem_u32(Asm);

    // cp.async issue: 64 rows x 4 chunks of 16B (32 halves per row)
    int lrow = tid >> 2;
    int lch  = tid & 3;
    int gr   = min(m0 + lrow, M - 1);
    const __half* gsrc_row = A + (size_t)gr * K + lch * 8;
    unsigned sdst_row = sbase + (unsigned)((lrow * SROW + lch * 8) * 2);

    auto issueA = [&](int t) {
        CP_ASYNC16(sdst_row + (unsigned)((t & 3) * STG * 2),
                   gsrc_row + t * 32);
    };

    float c[NT][4];
    #pragma unroll
    for (int ni = 0; ni < NT; ni++)
        #pragma unroll
        for (int j = 0; j < 4; j++) c[ni][j] = 0.0f;

    // prologue: 3 stages in flight (TILES >= 4 for all our shapes)
    #pragma unroll
    for (int s = 0; s < 3; s++) {
        issueA(s);
        CP_COMMIT();
    }

    // ldmatrix lane address: row wr*16 + (lane&15), col halves (lane>>4)*8
    unsigned lm_base = sbase +
        (unsigned)(((wr * 16 + (lane & 15)) * SROW + (lane >> 4) * 8) * 2);

    for (int t = 0; t < TILES; t++) {
        CP_WAIT2();               // stage t complete
        __syncthreads();          // everyone done reading stage (t-1)&3 too
        if (t + 3 < TILES) issueA(t + 3);   // writes buffer (t-1)&3 — now free
        CP_COMMIT();

        unsigned stg_off = (unsigned)((t & 3) * STG * 2);
        #pragma unroll
        for (int ks = 0; ks < 2; ks++) {
            uint2 bf[NT];
            #pragma unroll
            for (int ni = 0; ni < NT; ni++)
                bf[ni] = __ldg((const uint2*)(Wp +
                    (((t * 2 + ks) * NTT + wc * NT + ni) * 64 + lane * 2)));
            unsigned a0, a1, a2, a3;
            asm volatile(
                "ldmatrix.sync.aligned.m8n8.x4.shared.b16 {%0,%1,%2,%3}, [%4];"
                : "=r"(a0), "=r"(a1), "=r"(a2), "=r"(a3)
                : "r"(lm_base + stg_off + (unsigned)(ks * 32)));
            #pragma unroll
            for (int ni = 0; ni < NT; ni++) {
                asm volatile(
                    "mma.sync.aligned.m16n8k16.row.col.f32.f16.f16.f32 "
                    "{%0,%1,%2,%3}, {%4,%5,%6,%7}, {%8,%9}, {%0,%1,%2,%3};"
                    : "+f"(c[ni][0]), "+f"(c[ni][1]),
                      "+f"(c[ni][2]), "+f"(c[ni][3])
                    : "r"(a0), "r"(a1), "r"(a2), "r"(a3),
                      "r"(bf[ni].x), "r"(bf[ni].y));
            }
        }
    }

    int row = m0 + wr * 16 + qr;
    #pragma unroll
    for (int ni = 0; ni < NT; ni++) {
        int col = wc * NPW + ni * 8 + 2 * qc;
        if (row < M) {
            *(__half2*)(C + (size_t)row * NOUT + col) =
                __floats2half2_rn(c[ni][0], c[ni][1]);
        }
        if (row + 8 < M) {
            *(__half2*)(C + (size_t)(row + 8) * NOUT + col) =
                __floats2half2_rn(c[ni][2], c[ni][3]);
        }
    }
}

// ---------------- aggregation: out[v] = sum_{(s->v)} t[s]*w + t[v]*dinv[v]^2 + b
// Reads g_th (fp16), fp32 accumulate. TO_TMP: writes g_hh (fp16); else fp32 outp.
template <int D, bool RELU, bool TO_TMP>
__global__ void agg_kernel(const float* __restrict__ bias,
                           float* __restrict__ outp, int n) {
    const __half* __restrict__ t = g_th;
    constexpr int GS  = D / 4;
    constexpr int GPB = 128 / GS;
    int g = blockIdx.x * GPB + threadIdx.x / GS;
    if (g >= n) return;
    int lane = threadIdx.x % GS;
    int c = lane * 4;

    float dv = g_dinv[g];
    float sc = dv * dv;
    float4 b4 = *(const float4*)(bias + c);

    __half2 sv0, sv1;
    {
        uint2 raw = *(const uint2*)(t + (size_t)g * D + c);
        sv0 = *reinterpret_cast<__half2*>(&raw.x);
        sv1 = *reinterpret_cast<__half2*>(&raw.y);
    }
    float2 f0 = __half22float2(sv0);
    float2 f1 = __half22float2(sv1);
    float4 acc;
    acc.x = f0.x * sc + b4.x;
    acc.y = f0.y * sc + b4.y;
    acc.z = f1.x * sc + b4.z;
    acc.w = f1.y * sc + b4.w;

    int e0 = g_rowptr[g], e1 = g_rowptr[g + 1];
    for (int e = e0; e < e1; e++) {
        int s   = g_cidx[e];
        float w = g_w[e];
        uint2 raw = *(const uint2*)(t + (size_t)s * D + c);
        float2 h0 = __half22float2(*reinterpret_cast<__half2*>(&raw.x));
        float2 h1 = __half22float2(*reinterpret_cast<__half2*>(&raw.y));
        acc.x += h0.x * w;
        acc.y += h0.y * w;
        acc.z += h1.x * w;
        acc.w += h1.y * w;
    }
    if (RELU) {
        acc.x = fmaxf(acc.x, 0.f);
        acc.y = fmaxf(acc.y, 0.f);
        acc.z = fmaxf(acc.z, 0.f);
        acc.w = fmaxf(acc.w, 0.f);
    }
    if (TO_TMP) {
        __half2 o0 = __floats2half2_rn(acc.x, acc.y);
        __half2 o1 = __floats2half2_rn(acc.z, acc.w);
        uint2 packed = make_uint2(*reinterpret_cast<unsigned*>(&o0),
                                  *reinterpret_cast<unsigned*>(&o1));
        *(uint2*)(g_hh + (size_t)g * D + c) = packed;
    } else {
        *(float4*)(outp + (size_t)g * D + c) = acc;
    }
}

// ---------------- launch ----------------
extern "C" void kernel_launch(void* const* d_in, const int* in_sizes, int n_in,
                              void* d_out, int out_size) {
    const float* x     = (const float*)d_in[0];
    const int*   ei    = (const int*)d_in[1];
    const float* gamma = (const float*)d_in[2];
    const float* beta  = (const float*)d_in[3];
    const float* W1    = (const float*)d_in[4];
    const float* b1    = (const float*)d_in[5];
    const float* W2    = (const float*)d_in[6];
    const float* b2    = (const float*)d_in[7];
    const float* W3    = (const float*)d_in[8];
    const float* b3    = (const float*)d_in[9];
    float* out = (float*)d_out;

    int n  = in_sizes[0] / IN_DIM;
    int e  = in_sizes[1] / 2;
    int nb = (n + 255) / 256;

    wpack_all_kernel<<<(16384 + 8192 + 4096 + 255) / 256, 256>>>(W1, W2, W3);
    ln_apply_kernel<<<(n + 7) / 8, 256>>>(x, gamma, beta, n);
    zero_deg_kernel<<<(n + 255) / 256, 256>>>(n);

    gemm_tc_kernel<IN_DIM, HID, 0, 1><<<(n + 63) / 64, 256>>>(n);

    count_kernel<<<(e + 255) / 256, 256>>>(ei, e, n);
    scan_blocks_kernel<<<nb, 256>>>(n);          // also computes dinv
    scan_sums_kernel<<<1, 256>>>(nb, n);
    scan_add_kernel<<<nb, 256>>>(n);
    scatter_kernel<<<(e + 255) / 256, 256>>>(ei, e, n);

    agg_kernel<HID, true, true><<<(n + 3) / 4, 128>>>(b1, nullptr, n);

    gemm_tc_kernel<HID, HID, 1, 2><<<(n + 63) / 64, 256>>>(n);
    agg_kernel<HID, true, true><<<(n + 3) / 4, 128>>>(b2, nullptr, n);

    gemm_tc_kernel<HID, ZDIM, 1, 3><<<(n + 63) / 64, 256>>>(n);
    agg_kernel<ZDIM, false, false><<<(n + 7) / 8, 128>>>(b3, out, n);
}

// round 16
// speedup vs baseline: 1.6383x; 1.0676x over previous
#include <cuda_runtime.h>
#include <cuda_bf16.h>
#include <cuda_fp16.h>
#include <cstddef>

#define NMAX   50000
#define EMAX   800000
#define IN_DIM 256
#define HID    128
#define ZDIM   64
#define LN_EPS 1e-5f

// ---------------- device scratch (static, no allocation) ----------------
__device__ __half   g_xh[(size_t)NMAX * IN_DIM]; // layernormed input, fp16
__device__ __half   g_th[(size_t)NMAX * HID];    // GEMM output, fp16
__device__ __half   g_hh[(size_t)NMAX * HID];    // layer output after agg+relu, fp16
__device__ float    g_dinv[NMAX];
__device__ float    g_w  [EMAX];                 // per-edge coef dinv[s]*dinv[d]
__device__ int      g_deg[NMAX];
__device__ int      g_rowptr[NMAX + 1];
__device__ int      g_cursor[NMAX];
__device__ int      g_cidx[EMAX];                // src indices sorted by dst
__device__ int      g_bsum[256];
__device__ int      g_boff[256];
// pre-packed W in mma B-fragment order (uint = half2)
__device__ unsigned g_w1p[(IN_DIM/16) * (HID/8)  * 64];  // 16384
__device__ unsigned g_w2p[(HID/16)    * (HID/8)  * 64];  // 8192
__device__ unsigned g_w3p[(HID/16)    * (ZDIM/8) * 64];  // 4096

#define WPACK_TOT   (16384 + 8192 + 4096)
#define WPACK_BLKS  ((WPACK_TOT + 255) / 256)

__device__ __forceinline__ int clampi(int v, int lo, int hi) {
    return min(max(v, lo), hi);
}

#define CP_ASYNC16(dst, src) \
    asm volatile("cp.async.ca.shared.global [%0], [%1], 16;" \
                 :: "r"(dst), "l"(src))
#define CP_COMMIT() asm volatile("cp.async.commit_group;" ::: "memory")
#define CP_WAIT2()  asm volatile("cp.async.wait_group 2;"  ::: "memory")

__device__ __forceinline__ unsigned smem_u32(const void* p) {
    unsigned a;
    asm("{ .reg .u64 t; cvta.to.shared.u64 t, %1; cvt.u32.u64 %0, t; }"
        : "=r"(a) : "l"(p));
    return a;
}

// ---------------- W pre-pack: fragment order for m16n8k16 B operand --------
template <int K, int NOUT>
__device__ __forceinline__ void wpack_one(unsigned* dst,
                                          const float* __restrict__ W, int u) {
    constexpr int NTT = NOUT / 8;
    int reg  = u & 1;
    int lane = (u >> 1) & 31;
    int rest = u >> 6;
    int ni   = rest % NTT;
    int ksg  = rest / NTT;
    int col  = ni * 8 + (lane >> 2);
    int k    = ksg * 16 + (lane & 3) * 2 + reg * 8;
    __half2 h = __floats2half2_rn(W[(size_t)k * NOUT + col],
                                  W[(size_t)(k + 1) * NOUT + col]);
    dst[u] = *reinterpret_cast<unsigned*>(&h);
}

// ---------------- LN body: one warp per 256-wide row -----------------------
__device__ __forceinline__ void ln_row(const float* __restrict__ x,
                                       const float* __restrict__ gamma,
                                       const float* __restrict__ beta,
                                       int row, int lane) {
    const float* xr = x + (size_t)row * IN_DIM;
    float4 v0 = *(const float4*)(xr + lane * 8);
    float4 v1 = *(const float4*)(xr + lane * 8 + 4);

    float s  = v0.x + v0.y + v0.z + v0.w + v1.x + v1.y + v1.z + v1.w;
    float sq = v0.x*v0.x + v0.y*v0.y + v0.z*v0.z + v0.w*v0.w
             + v1.x*v1.x + v1.y*v1.y + v1.z*v1.z + v1.w*v1.w;
    #pragma unroll
    for (int off = 16; off > 0; off >>= 1) {
        s  += __shfl_xor_sync(0xffffffffu, s,  off);
        sq += __shfl_xor_sync(0xffffffffu, sq, off);
    }
    float mu  = s * (1.0f / IN_DIM);
    float var = sq * (1.0f / IN_DIM) - mu * mu;
    float rs  = rsqrtf(var + LN_EPS);

    float4 g0 = *(const float4*)(gamma + lane * 8);
    float4 g1 = *(const float4*)(gamma + lane * 8 + 4);
    float4 b0 = *(const float4*)(beta + lane * 8);
    float4 b1 = *(const float4*)(beta + lane * 8 + 4);

    __half2 o[4];
    o[0] = __floats2half2_rn((v0.x - mu) * rs * g0.x + b0.x,
                             (v0.y - mu) * rs * g0.y + b0.y);
    o[1] = __floats2half2_rn((v0.z - mu) * rs * g0.z + b0.z,
                             (v0.w - mu) * rs * g0.w + b0.w);
    o[2] = __floats2half2_rn((v1.x - mu) * rs * g1.x + b1.x,
                             (v1.y - mu) * rs * g1.y + b1.y);
    o[3] = __floats2half2_rn((v1.z - mu) * rs * g1.z + b1.z,
                             (v1.w - mu) * rs * g1.w + b1.w);
    *(uint4*)(g_xh + (size_t)row * IN_DIM + lane * 8) =
        *reinterpret_cast<uint4*>(o);
}

// ---------------- K1: wpack || layernorm || zero_deg -----------------------
__global__ void prep_kernel(const float* __restrict__ W1,
                            const float* __restrict__ W2,
                            const float* __restrict__ W3,
                            const float* __restrict__ x,
                            const float* __restrict__ gamma,
                            const float* __restrict__ beta,
                            int n, int nln) {
    int b = blockIdx.x;
    if (b < WPACK_BLKS) {
        int u = b * 256 + threadIdx.x;
        if (u < 16384)                    wpack_one<IN_DIM, HID>(g_w1p, W1, u);
        else if (u < 16384 + 8192)        wpack_one<HID, HID>(g_w2p, W2, u - 16384);
        else if (u < WPACK_TOT)           wpack_one<HID, ZDIM>(g_w3p, W3, u - 24576);
    } else if (b < WPACK_BLKS + nln) {
        int row = (b - WPACK_BLKS) * 8 + (threadIdx.x >> 5);
        if (row < n) ln_row(x, gamma, beta, row, threadIdx.x & 31);
    } else {
        int i = (b - WPACK_BLKS - nln) * 256 + threadIdx.x;
        if (i < n) g_deg[i] = 0;
    }
}

// ---------------- fp16 GEMM body: g_th[.] = A @ W --------------------------
// A: fp16 row-major, cp.async pipeline (4 buffers, 3 in flight), ldmatrix.x4.
// B: direct LDG.64 from pre-packed fragment-order W (L2-resident).
// 8 warps = 4 m16 strips x 2 col halves. BM=64, BK=32.
template <int K, int NOUT, int ASEL, int WSEL>
__device__ __forceinline__ void gemm_body(int M, int bid) {
    const __half* __restrict__ A = (ASEL == 0) ? g_xh : g_hh;
    const unsigned* __restrict__ Wp =
        (WSEL == 1) ? g_w1p : (WSEL == 2) ? g_w2p : g_w3p;
    __half* __restrict__ C = g_th;

    constexpr int BM   = 64;
    constexpr int NPW  = NOUT / 2;
    constexpr int NT   = NPW / 8;
    constexpr int NTT  = NOUT / 8;
    constexpr int SROW = 40;
    constexpr int STG  = BM * SROW;
    constexpr int TILES = K / 32;

    __shared__ alignas(16) __half Asm[4 * STG];

    int tid  = threadIdx.x;
    int wid  = tid >> 5;
    int lane = tid & 31;
    int qr   = lane >> 2;
    int qc   = lane & 3;
    int wr   = wid >> 1;
    int wc   = wid & 1;
    int m0   = bid * BM;

    unsigned sbase = smem_u32(Asm);

    int lrow = tid >> 2;
    int lch  = tid & 3;
    int gr   = min(m0 + lrow, M - 1);
    const __half* gsrc_row = A + (size_t)gr * K + lch * 8;
    unsigned sdst_row = sbase + (unsigned)((lrow * SROW + lch * 8) * 2);

    auto issueA = [&](int t) {
        CP_ASYNC16(sdst_row + (unsigned)((t & 3) * STG * 2),
                   gsrc_row + t * 32);
    };

    float c[NT][4];
    #pragma unroll
    for (int ni = 0; ni < NT; ni++)
        #pragma unroll
        for (int j = 0; j < 4; j++) c[ni][j] = 0.0f;

    #pragma unroll
    for (int s = 0; s < 3; s++) {
        issueA(s);
        CP_COMMIT();
    }

    unsigned lm_base = sbase +
        (unsigned)(((wr * 16 + (lane & 15)) * SROW + (lane >> 4) * 8) * 2);

    for (int t = 0; t < TILES; t++) {
        CP_WAIT2();
        __syncthreads();
        if (t + 3 < TILES) issueA(t + 3);
        CP_COMMIT();

        unsigned stg_off = (unsigned)((t & 3) * STG * 2);
        #pragma unroll
        for (int ks = 0; ks < 2; ks++) {
            uint2 bf[NT];
            #pragma unroll
            for (int ni = 0; ni < NT; ni++)
                bf[ni] = __ldg((const uint2*)(Wp +
                    (((t * 2 + ks) * NTT + wc * NT + ni) * 64 + lane * 2)));
            unsigned a0, a1, a2, a3;
            asm volatile(
                "ldmatrix.sync.aligned.m8n8.x4.shared.b16 {%0,%1,%2,%3}, [%4];"
                : "=r"(a0), "=r"(a1), "=r"(a2), "=r"(a3)
                : "r"(lm_base + stg_off + (unsigned)(ks * 32)));
            #pragma unroll
            for (int ni = 0; ni < NT; ni++) {
                asm volatile(
                    "mma.sync.aligned.m16n8k16.row.col.f32.f16.f16.f32 "
                    "{%0,%1,%2,%3}, {%4,%5,%6,%7}, {%8,%9}, {%0,%1,%2,%3};"
                    : "+f"(c[ni][0]), "+f"(c[ni][1]),
                      "+f"(c[ni][2]), "+f"(c[ni][3])
                    : "r"(a0), "r"(a1), "r"(a2), "r"(a3),
                      "r"(bf[ni].x), "r"(bf[ni].y));
            }
        }
    }

    int row = m0 + wr * 16 + qr;
    #pragma unroll
    for (int ni = 0; ni < NT; ni++) {
        int col = wc * NPW + ni * 8 + 2 * qc;
        if (row < M) {
            *(__half2*)(C + (size_t)row * NOUT + col) =
                __floats2half2_rn(c[ni][0], c[ni][1]);
        }
        if (row + 8 < M) {
            *(__half2*)(C + (size_t)(row + 8) * NOUT + col) =
                __floats2half2_rn(c[ni][2], c[ni][3]);
        }
    }
}

// ---------------- K2: GEMM1 || count ---------------------------------------
__global__ void __launch_bounds__(256, 3)
gemm1_count_kernel(const int* __restrict__ ei, int e, int n, int gblk) {
    if (blockIdx.x < gblk) {
        gemm_body<IN_DIM, HID, 0, 1>(n, blockIdx.x);
    } else {
        int i = (blockIdx.x - gblk) * 256 + threadIdx.x;
        if (i < e) {
            int d = clampi(ei[e + i], 0, n - 1);
            atomicAdd(&g_deg[d], 1);
        }
    }
}

template <int K, int NOUT, int ASEL, int WSEL>
__global__ void __launch_bounds__(256, 3)
gemm_tc_kernel(int M) {
    gemm_body<K, NOUT, ASEL, WSEL>(M, blockIdx.x);
}

// ---------------- 3-phase multi-block exclusive scan of g_deg ----------------
// phase 1 also computes g_dinv (fused).
__global__ void scan_blocks_kernel(int n) {
    __shared__ int ws[8];
    int i = blockIdx.x * 256 + threadIdx.x;
    int lane = threadIdx.x & 31, wid = threadIdx.x >> 5;
    int v = (i < n) ? g_deg[i] : 0;
    if (i < n) g_dinv[i] = rsqrtf(1.0f + (float)v);
    int x = v;
    #pragma unroll
    for (int off = 1; off < 32; off <<= 1) {
        int y = __shfl_up_sync(0xffffffffu, x, off);
        if (lane >= off) x += y;
    }
    if (lane == 31) ws[wid] = x;
    __syncthreads();
    if (wid == 0) {
        int w = (lane < 8) ? ws[lane] : 0;
        #pragma unroll
        for (int off = 1; off < 8; off <<= 1) {
            int y = __shfl_up_sync(0xffffffffu, w, off);
            if (lane >= off) w += y;
        }
        if (lane < 8) ws[lane] = w;
    }
    __syncthreads();
    int woff = wid ? ws[wid - 1] : 0;
    if (i < n) g_rowptr[i] = woff + x - v;
    if (threadIdx.x == 255) g_bsum[blockIdx.x] = woff + x;
}

__global__ void scan_sums_kernel(int nb, int n) {
    __shared__ int ws[8];
    int b = threadIdx.x;
    int lane = b & 31, wid = b >> 5;
    int v = (b < nb) ? g_bsum[b] : 0;
    int x = v;
    #pragma unroll
    for (int off = 1; off < 32; off <<= 1) {
        int y = __shfl_up_sync(0xffffffffu, x, off);
        if (lane >= off) x += y;
    }
    if (lane == 31) ws[wid] = x;
    __syncthreads();
    if (wid == 0) {
        int w = (lane < 8) ? ws[lane] : 0;
        #pragma unroll
        for (int off = 1; off < 8; off <<= 1) {
            int y = __shfl_up_sync(0xffffffffu, w, off);
            if (lane >= off) w += y;
        }
        if (lane < 8) ws[lane] = w;
    }
    __syncthreads();
    int woff = wid ? ws[wid - 1] : 0;
    g_boff[b] = woff + x - v;
    if (b == 255) g_rowptr[n] = woff + x;
}

__global__ void scan_add_kernel(int n) {
    int i = blockIdx.x * 256 + threadIdx.x;
    if (i >= n) return;
    int rp = g_rowptr[i] + g_boff[i >> 8];
    g_rowptr[i] = rp;
    g_cursor[i] = rp;
}

__global__ void scatter_kernel(const int* __restrict__ ei, int e, int n) {
    int i = blockIdx.x * blockDim.x + threadIdx.x;
    if (i >= e) return;
    int s = clampi(ei[i],     0, n - 1);
    int d = clampi(ei[e + i], 0, n - 1);
    int pos = atomicAdd(&g_cursor[d], 1);
    g_cidx[pos] = s;
    g_w[pos] = g_dinv[s] * g_dinv[d];
}

// ---------------- aggregation: out[v] = sum_{(s->v)} t[s]*w + t[v]*dinv[v]^2 + b
// Reads g_th (fp16), fp32 accumulate. TO_TMP: writes g_hh (fp16); else fp32 outp.
template <int D, bool RELU, bool TO_TMP>
__global__ void agg_kernel(const float* __restrict__ bias,
                           float* __restrict__ outp, int n) {
    const __half* __restrict__ t = g_th;
    constexpr int GS  = D / 4;
    constexpr int GPB = 128 / GS;
    int g = blockIdx.x * GPB + threadIdx.x / GS;
    if (g >= n) return;
    int lane = threadIdx.x % GS;
    int c = lane * 4;

    float dv = g_dinv[g];
    float sc = dv * dv;
    float4 b4 = *(const float4*)(bias + c);

    __half2 sv0, sv1;
    {
        uint2 raw = *(const uint2*)(t + (size_t)g * D + c);
        sv0 = *reinterpret_cast<__half2*>(&raw.x);
        sv1 = *reinterpret_cast<__half2*>(&raw.y);
    }
    float2 f0 = __half22float2(sv0);
    float2 f1 = __half22float2(sv1);
    float4 acc;
    acc.x = f0.x * sc + b4.x;
    acc.y = f0.y * sc + b4.y;
    acc.z = f1.x * sc + b4.z;
    acc.w = f1.y * sc + b4.w;

    int e0 = g_rowptr[g], e1 = g_rowptr[g + 1];
    for (int e = e0; e < e1; e++) {
        int s   = g_cidx[e];
        float w = g_w[e];
        uint2 raw = *(const uint2*)(t + (size_t)s * D + c);
        float2 h0 = __half22float2(*reinterpret_cast<__half2*>(&raw.x));
        float2 h1 = __half22float2(*reinterpret_cast<__half2*>(&raw.y));
        acc.x += h0.x * w;
        acc.y += h0.y * w;
        acc.z += h1.x * w;
        acc.w += h1.y * w;
    }
    if (RELU) {
        acc.x = fmaxf(acc.x, 0.f);
        acc.y = fmaxf(acc.y, 0.f);
        acc.z = fmaxf(acc.z, 0.f);
        acc.w = fmaxf(acc.w, 0.f);
    }
    if (TO_TMP) {
        __half2 o0 = __floats2half2_rn(acc.x, acc.y);
        __half2 o1 = __floats2half2_rn(acc.z, acc.w);
        uint2 packed = make_uint2(*reinterpret_cast<unsigned*>(&o0),
                                  *reinterpret_cast<unsigned*>(&o1));
        *(uint2*)(g_hh + (size_t)g * D + c) = packed;
    } else {
        *(float4*)(outp + (size_t)g * D + c) = acc;
    }
}

// ---------------- launch ----------------
extern "C" void kernel_launch(void* const* d_in, const int* in_sizes, int n_in,
                              void* d_out, int out_size) {
    const float* x     = (const float*)d_in[0];
    const int*   ei    = (const int*)d_in[1];
    const float* gamma = (const float*)d_in[2];
    const float* beta  = (const float*)d_in[3];
    const float* W1    = (const float*)d_in[4];
    const float* b1    = (const float*)d_in[5];
    const float* W2    = (const float*)d_in[6];
    const float* b2    = (const float*)d_in[7];
    const float* W3    = (const float*)d_in[8];
    const float* b3    = (const float*)d_in[9];
    float* out = (float*)d_out;

    int n  = in_sizes[0] / IN_DIM;
    int e  = in_sizes[1] / 2;
    int nb = (n + 255) / 256;
    int nln = (n + 7) / 8;
    int gblk = (n + 63) / 64;
    int cblk = (e + 255) / 256;

    // K1: wpack || layernorm || zero_deg (all independent)
    prep_kernel<<<WPACK_BLKS + nln + nb, 256>>>(W1, W2, W3, x, gamma, beta, n, nln);

    // K2: GEMM1 (needs ln) || count (needs zero) — independent of each other
    gemm1_count_kernel<<<gblk + cblk, 256>>>(ei, e, n, gblk);

    scan_blocks_kernel<<<nb, 256>>>(n);          // also computes dinv
    scan_sums_kernel<<<1, 256>>>(nb, n);
    scan_add_kernel<<<nb, 256>>>(n);
    scatter_kernel<<<cblk, 256>>>(ei, e, n);

    agg_kernel<HID, true, true><<<(n + 3) / 4, 128>>>(b1, nullptr, n);

    gemm_tc_kernel<HID, HID, 1, 2><<<gblk, 256>>>(n);
    agg_kernel<HID, true, true><<<(n + 3) / 4, 128>>>(b2, nullptr, n);

    gemm_tc_kernel<HID, ZDIM, 1, 3><<<gblk, 256>>>(n);
    agg_kernel<ZDIM, false, false><<<(n + 7) / 8, 128>>>(b3, out, n);
}